// round 1
// baseline (speedup 1.0000x reference)
#include <cuda_runtime.h>
#include <math.h>

// Problem dims (fixed by the dataset)
#define BB   16
#define LL   512
#define DIN  1024
#define DH   1024
#define MTOT (BB * LL)   // 8192

// ---------------- scratch (static __device__: allocation-free) --------------
__device__ float g_ori  [(size_t)MTOT * DH];
__device__ float g_t0   [(size_t)MTOT * DH];
__device__ float g_tar  [(size_t)MTOT * DH];
__device__ float g_ofc  [(size_t)MTOT * DH];
__device__ float g_otp  [(size_t)MTOT * DH];
__device__ float g_obuf [(size_t)MTOT * DH];
__device__ float g_Q    [(size_t)BB * LL * LL];
__device__ float g_itn  [MTOT];
__device__ float g_ifn  [MTOT];
__device__ float g_u    [MTOT];
__device__ float g_v    [MTOT];
__device__ float g_rs   [MTOT];

// ---------------- block reduction helper ------------------------------------
__device__ __forceinline__ float block_reduce_sum_256(float val, float* red) {
    int tid = threadIdx.x;
    #pragma unroll
    for (int o = 16; o > 0; o >>= 1) val += __shfl_down_sync(0xffffffffu, val, o);
    if ((tid & 31) == 0) red[tid >> 5] = val;
    __syncthreads();
    if (tid < 8) {
        val = red[tid];
        #pragma unroll
        for (int o = 4; o > 0; o >>= 1) val += __shfl_down_sync(0xffu, val, o);
        if (tid == 0) red[0] = val;
    }
    __syncthreads();
    float r = red[0];
    __syncthreads();
    return r;
}

// ---------------- GEMM: C[M,N] = A[M,K] @ W[K,N] + bias ----------------------
// 128x128 tile, BK=8, 256 threads, 8x8 per thread.
#define BM 128
#define BN 128
#define BK 8

__global__ __launch_bounds__(256) void gemm_bias_kernel(
    const float* __restrict__ A, const float* __restrict__ W,
    const float* __restrict__ bias, float* __restrict__ C,
    int M, int N, int K)
{
    __shared__ float As[BK][BM];
    __shared__ float Bs[BK][BN];
    int tid = threadIdx.x;
    int bm = blockIdx.y * BM;
    int bn = blockIdx.x * BN;
    int tx = tid & 15, ty = tid >> 4;

    float acc[8][8];
    #pragma unroll
    for (int i = 0; i < 8; i++)
        #pragma unroll
        for (int j = 0; j < 8; j++) acc[i][j] = 0.f;

    int arow = tid >> 1, ak = (tid & 1) * 4;        // A loader: 128 rows x 8 k
    int bk  = tid >> 5, bn4 = (tid & 31) * 4;       // B loader: 8 k x 128 n
    const float* Aptr = A + (size_t)(bm + arow) * K + ak;
    const float* Wptr = W + (size_t)bk * N + bn + bn4;

    for (int k0 = 0; k0 < K; k0 += BK) {
        float4 av = *(const float4*)(Aptr + k0);
        As[ak + 0][arow] = av.x; As[ak + 1][arow] = av.y;
        As[ak + 2][arow] = av.z; As[ak + 3][arow] = av.w;
        float4 bv = *(const float4*)(Wptr + (size_t)k0 * N);
        *(float4*)&Bs[bk][bn4] = bv;
        __syncthreads();
        #pragma unroll
        for (int kk = 0; kk < BK; kk++) {
            float4 a0 = *(const float4*)&As[kk][ty * 8];
            float4 a1 = *(const float4*)&As[kk][ty * 8 + 4];
            float4 b0 = *(const float4*)&Bs[kk][tx * 8];
            float4 b1 = *(const float4*)&Bs[kk][tx * 8 + 4];
            float ra[8] = {a0.x, a0.y, a0.z, a0.w, a1.x, a1.y, a1.z, a1.w};
            float rb[8] = {b0.x, b0.y, b0.z, b0.w, b1.x, b1.y, b1.z, b1.w};
            #pragma unroll
            for (int i = 0; i < 8; i++)
                #pragma unroll
                for (int j = 0; j < 8; j++) acc[i][j] += ra[i] * rb[j];
        }
        __syncthreads();
    }

    #pragma unroll
    for (int i = 0; i < 8; i++) {
        int row = bm + ty * 8 + i;
        #pragma unroll
        for (int j = 0; j < 8; j++) {
            int col = bn + tx * 8 + j;
            C[(size_t)row * N + col] = acc[i][j] + bias[col];
        }
    }
}

// ---------------- Q-GEMM (NT, batched): Q = exp(20 * cos_sim) ----------------
// A = tar[b] [L,DH] row-major, B = ofc[b] [L,DH] row-major; C[t][o] over K=DH.
__global__ __launch_bounds__(256) void qgemm_kernel(
    const float* __restrict__ tar, const float* __restrict__ ofc,
    const float* __restrict__ itn, const float* __restrict__ ifn,
    float* __restrict__ Q)
{
    const int K = DH;
    int b = blockIdx.z;
    const float* A  = tar + (size_t)b * LL * DH;
    const float* Bm = ofc + (size_t)b * LL * DH;

    __shared__ float As[BK][BM];
    __shared__ float Bs[BK][BN];
    int tid = threadIdx.x;
    int bm = blockIdx.y * BM;
    int bn = blockIdx.x * BN;
    int tx = tid & 15, ty = tid >> 4;

    float acc[8][8];
    #pragma unroll
    for (int i = 0; i < 8; i++)
        #pragma unroll
        for (int j = 0; j < 8; j++) acc[i][j] = 0.f;

    int arow = tid >> 1, ak = (tid & 1) * 4;
    const float* Aptr = A  + (size_t)(bm + arow) * K + ak;
    const float* Bptr = Bm + (size_t)(bn + arow) * K + ak;

    for (int k0 = 0; k0 < K; k0 += BK) {
        float4 av = *(const float4*)(Aptr + k0);
        As[ak + 0][arow] = av.x; As[ak + 1][arow] = av.y;
        As[ak + 2][arow] = av.z; As[ak + 3][arow] = av.w;
        float4 bv = *(const float4*)(Bptr + k0);
        Bs[ak + 0][arow] = bv.x; Bs[ak + 1][arow] = bv.y;
        Bs[ak + 2][arow] = bv.z; Bs[ak + 3][arow] = bv.w;
        __syncthreads();
        #pragma unroll
        for (int kk = 0; kk < BK; kk++) {
            float4 a0 = *(const float4*)&As[kk][ty * 8];
            float4 a1 = *(const float4*)&As[kk][ty * 8 + 4];
            float4 b0 = *(const float4*)&Bs[kk][tx * 8];
            float4 b1 = *(const float4*)&Bs[kk][tx * 8 + 4];
            float ra[8] = {a0.x, a0.y, a0.z, a0.w, a1.x, a1.y, a1.z, a1.w};
            float rb[8] = {b0.x, b0.y, b0.z, b0.w, b1.x, b1.y, b1.z, b1.w};
            #pragma unroll
            for (int i = 0; i < 8; i++)
                #pragma unroll
                for (int j = 0; j < 8; j++) acc[i][j] += ra[i] * rb[j];
        }
        __syncthreads();
    }

    #pragma unroll
    for (int i = 0; i < 8; i++) {
        int t = bm + ty * 8 + i;
        float sc_t = itn[b * LL + t] * 20.0f;   // 1/OT_REG = 20
        #pragma unroll
        for (int j = 0; j < 8; j++) {
            int o = bn + tx * 8 + j;
            float c = acc[i][j] * sc_t * ifn[b * LL + o];
            Q[((size_t)b * LL + t) * LL + o] = expf(c);
        }
    }
}

// ---------------- Final GEMM (NN, batched): out = rs_t*(Q @ (v*otp)) + tar ---
__global__ __launch_bounds__(256) void fgemm_kernel(
    const float* __restrict__ Q, const float* __restrict__ otp,
    const float* __restrict__ v, const float* __restrict__ rs,
    const float* __restrict__ tar, float* __restrict__ out)
{
    const int K = LL;   // 512
    const int N = DH;
    int b = blockIdx.z;
    const float* A  = Q   + (size_t)b * LL * LL;
    const float* Bm = otp + (size_t)b * LL * DH;

    __shared__ float As[BK][BM];
    __shared__ float Bs[BK][BN];
    int tid = threadIdx.x;
    int bm = blockIdx.y * BM;
    int bn = blockIdx.x * BN;
    int tx = tid & 15, ty = tid >> 4;

    float acc[8][8];
    #pragma unroll
    for (int i = 0; i < 8; i++)
        #pragma unroll
        for (int j = 0; j < 8; j++) acc[i][j] = 0.f;

    int arow = tid >> 1, ak = (tid & 1) * 4;
    int bk  = tid >> 5, bn4 = (tid & 31) * 4;
    const float* Aptr = A  + (size_t)(bm + arow) * K + ak;
    const float* Bptr = Bm + (size_t)bk * N + bn + bn4;
    const float* vv   = v + b * LL;

    for (int k0 = 0; k0 < K; k0 += BK) {
        float4 av = *(const float4*)(Aptr + k0);
        As[ak + 0][arow] = av.x; As[ak + 1][arow] = av.y;
        As[ak + 2][arow] = av.z; As[ak + 3][arow] = av.w;
        float vs = vv[k0 + bk];
        float4 bv = *(const float4*)(Bptr + (size_t)k0 * N);
        bv.x *= vs; bv.y *= vs; bv.z *= vs; bv.w *= vs;
        *(float4*)&Bs[bk][bn4] = bv;
        __syncthreads();
        #pragma unroll
        for (int kk = 0; kk < BK; kk++) {
            float4 a0 = *(const float4*)&As[kk][ty * 8];
            float4 a1 = *(const float4*)&As[kk][ty * 8 + 4];
            float4 b0 = *(const float4*)&Bs[kk][tx * 8];
            float4 b1 = *(const float4*)&Bs[kk][tx * 8 + 4];
            float ra[8] = {a0.x, a0.y, a0.z, a0.w, a1.x, a1.y, a1.z, a1.w};
            float rb[8] = {b0.x, b0.y, b0.z, b0.w, b1.x, b1.y, b1.z, b1.w};
            #pragma unroll
            for (int i = 0; i < 8; i++)
                #pragma unroll
                for (int j = 0; j < 8; j++) acc[i][j] += ra[i] * rb[j];
        }
        __syncthreads();
    }

    #pragma unroll
    for (int i = 0; i < 8; i++) {
        int t = bm + ty * 8 + i;
        int grow = b * LL + t;
        float r = rs[grow];
        #pragma unroll
        for (int j = 0; j < 8; j++) {
            int col = bn + tx * 8 + j;
            out[(size_t)grow * DH + col] = r * acc[i][j] + tar[(size_t)grow * DH + col];
        }
    }
}

// ---------------- row inverse-norm: inv[row] = 1/max(||x_row||, eps) ---------
__global__ __launch_bounds__(256) void row_invnorm_kernel(
    const float* __restrict__ x, float* __restrict__ inv, float eps)
{
    __shared__ float red[8];
    int row = blockIdx.x;
    const float* p = x + (size_t)row * DH;
    float s = 0.f;
    for (int c = threadIdx.x; c < DH; c += 256) { float v = p[c]; s += v * v; }
    float tot = block_reduce_sum_256(s, red);
    if (threadIdx.x == 0) inv[row] = 1.0f / fmaxf(sqrtf(tot), eps);
}

// ---------------- small vector kernels --------------------------------------
__global__ void set_ones_kernel(float* p, int n) {
    int i = blockIdx.x * blockDim.x + threadIdx.x;
    if (i < n) p[i] = 1.0f;
}

// u[b,t] = 1 / sum_o Q[b,t,o] * v[b,o]     (one warp per row)
__global__ void rowmv_kernel(const float* __restrict__ Q,
                             const float* __restrict__ v,
                             float* __restrict__ u)
{
    int t = blockIdx.x * 8 + threadIdx.y;
    int b = blockIdx.y;
    const float* row = Q + ((size_t)b * LL + t) * LL;
    const float* vv = v + b * LL;
    float s = 0.f;
    for (int o = threadIdx.x; o < LL; o += 32) s += row[o] * vv[o];
    #pragma unroll
    for (int off = 16; off > 0; off >>= 1) s += __shfl_down_sync(0xffffffffu, s, off);
    if (threadIdx.x == 0) u[b * LL + t] = 1.0f / s;
}

// v[b,o] = 1 / sum_t Q[b,t,o] * u[b,t]
__global__ void colmv_kernel(const float* __restrict__ Q,
                             const float* __restrict__ u,
                             float* __restrict__ v)
{
    __shared__ float red[8][32];
    int o = blockIdx.x * 32 + threadIdx.x;
    int b = blockIdx.y;
    const float* uu = u + b * LL;
    float s = 0.f;
    for (int t = threadIdx.y; t < LL; t += 8)
        s += Q[((size_t)b * LL + t) * LL + o] * uu[t];
    red[threadIdx.y][threadIdx.x] = s;
    __syncthreads();
    if (threadIdx.y == 0) {
        float tot = 0.f;
        #pragma unroll
        for (int j = 0; j < 8; j++) tot += red[j][threadIdx.x];
        v[b * LL + o] = 1.0f / tot;
    }
}

// rs[b,t] = u_t / max(u_t * sqrt(sum_o (Q_to * v_o)^2), 1e-12)
__global__ void rowscale_kernel(const float* __restrict__ Q,
                                const float* __restrict__ v,
                                const float* __restrict__ u,
                                float* __restrict__ rs)
{
    int t = blockIdx.x * 8 + threadIdx.y;
    int b = blockIdx.y;
    const float* row = Q + ((size_t)b * LL + t) * LL;
    const float* vv = v + b * LL;
    float s = 0.f;
    for (int o = threadIdx.x; o < LL; o += 32) {
        float q = row[o] * vv[o];
        s += q * q;
    }
    #pragma unroll
    for (int off = 16; off > 0; off >>= 1) s += __shfl_down_sync(0xffffffffu, s, off);
    if (threadIdx.x == 0) {
        float ut = u[b * LL + t];
        rs[b * LL + t] = ut / fmaxf(ut * sqrtf(s), 1e-12f);
    }
}

// ---------------- LayerNorm over last dim (1024) -----------------------------
__global__ __launch_bounds__(256) void ln_kernel(
    const float* __restrict__ x, const float* __restrict__ g,
    const float* __restrict__ beta, float* __restrict__ y)
{
    __shared__ float buf[DH];
    __shared__ float red[8];
    int row = blockIdx.x;
    const float* p = x + (size_t)row * DH;
    float s = 0.f;
    for (int c = threadIdx.x; c < DH; c += 256) { float v = p[c]; buf[c] = v; s += v; }
    float mean = block_reduce_sum_256(s, red) * (1.0f / DH);
    float s2 = 0.f;
    for (int c = threadIdx.x; c < DH; c += 256) { float d = buf[c] - mean; s2 += d * d; }
    float var = block_reduce_sum_256(s2, red) * (1.0f / DH);
    float inv = rsqrtf(var + 1e-5f);
    for (int c = threadIdx.x; c < DH; c += 256)
        y[(size_t)row * DH + c] = (buf[c] - mean) * inv * g[c] + beta[c];
}

// ---------------- launch -----------------------------------------------------
extern "C" void kernel_launch(void* const* d_in, const int* in_sizes, int n_in,
                              void* d_out, int out_size)
{
    const float* origin = (const float*)d_in[0];
    const float* target = (const float*)d_in[1];
    const float* W_ori = (const float*)d_in[2];  const float* b_ori = (const float*)d_in[3];
    const float* W_tar = (const float*)d_in[4];  const float* b_tar = (const float*)d_in[5];
    const float* W_ft  = (const float*)d_in[6];  const float* b_ft  = (const float*)d_in[7];
    const float* W_fo  = (const float*)d_in[8];  const float* b_fo  = (const float*)d_in[9];
    const float* W_fot = (const float*)d_in[10]; const float* b_fot = (const float*)d_in[11];
    const float* ln_g  = (const float*)d_in[12]; const float* ln_b  = (const float*)d_in[13];
    float* out = (float*)d_out;

    float *ori, *t0, *tar, *ofc, *otp, *obuf, *Q, *itn, *ifn, *u, *v, *rs;
    cudaGetSymbolAddress((void**)&ori,  g_ori);
    cudaGetSymbolAddress((void**)&t0,   g_t0);
    cudaGetSymbolAddress((void**)&tar,  g_tar);
    cudaGetSymbolAddress((void**)&ofc,  g_ofc);
    cudaGetSymbolAddress((void**)&otp,  g_otp);
    cudaGetSymbolAddress((void**)&obuf, g_obuf);
    cudaGetSymbolAddress((void**)&Q,    g_Q);
    cudaGetSymbolAddress((void**)&itn,  g_itn);
    cudaGetSymbolAddress((void**)&ifn,  g_ifn);
    cudaGetSymbolAddress((void**)&u,    g_u);
    cudaGetSymbolAddress((void**)&v,    g_v);
    cudaGetSymbolAddress((void**)&rs,   g_rs);

    dim3 blk(256);
    dim3 gBig(DH / BN, MTOT / BM);          // 8 x 64

    // 5 dense GEMMs
    gemm_bias_kernel<<<gBig, blk>>>(origin, W_ori, b_ori, ori, MTOT, DH, DIN);
    gemm_bias_kernel<<<gBig, blk>>>(target, W_tar, b_tar, t0,  MTOT, DH, DIN);
    gemm_bias_kernel<<<gBig, blk>>>(t0,     W_ft,  b_ft,  tar, MTOT, DH, DH);
    gemm_bias_kernel<<<gBig, blk>>>(ori,    W_fo,  b_fo,  ofc, MTOT, DH, DH);
    gemm_bias_kernel<<<gBig, blk>>>(ori,    W_fot, b_fot, otp, MTOT, DH, DH);

    // row inverse norms for cosine similarity
    row_invnorm_kernel<<<MTOT, blk>>>(tar, itn, 1e-8f);
    row_invnorm_kernel<<<MTOT, blk>>>(ofc, ifn, 1e-8f);

    // Q = exp(cos/0.05)
    qgemm_kernel<<<dim3(LL / BN, LL / BM, BB), blk>>>(tar, ofc, itn, ifn, Q);

    // Sinkhorn via scaling vectors: u = 1/(Qv), v = 1/(Q^T u), 5 iterations
    set_ones_kernel<<<(MTOT + 255) / 256, 256>>>(v, MTOT);
    for (int it = 0; it < 5; it++) {
        rowmv_kernel<<<dim3(LL / 8, BB), dim3(32, 8)>>>(Q, v, u);
        colmv_kernel<<<dim3(LL / 32, BB), dim3(32, 8)>>>(Q, u, v);
    }
    // per-row normalize scale for plan = l2norm(diag(u) Q diag(v), dim=-1)
    rowscale_kernel<<<dim3(LL / 8, BB), dim3(32, 8)>>>(Q, v, u, rs);

    // out = rs_t * (Q @ (v .* otp)) + tar
    fgemm_kernel<<<dim3(DH / BN, LL / BM, BB), blk>>>(Q, otp, v, rs, tar, obuf);

    // LayerNorm
    ln_kernel<<<MTOT, blk>>>(obuf, ln_g, ln_b, out);
}

// round 2
// speedup vs baseline: 1.0715x; 1.0715x over previous
#include <cuda_runtime.h>
#include <math.h>

// Problem dims (fixed by the dataset)
#define BB   16
#define LL   512
#define DIN  1024
#define DH   1024
#define MTOT (BB * LL)   // 8192

// ---------------- scratch (static __device__: allocation-free) --------------
__device__ float g_ori  [(size_t)MTOT * DH];
__device__ float g_t0   [(size_t)MTOT * DH];
__device__ float g_tar  [(size_t)MTOT * DH];
__device__ float g_ofc  [(size_t)MTOT * DH];
__device__ float g_otp  [(size_t)MTOT * DH];
__device__ float g_obuf [(size_t)MTOT * DH];
__device__ float g_Q    [(size_t)BB * LL * LL];
__device__ float g_itn  [MTOT];
__device__ float g_ifn  [MTOT];
__device__ float g_u    [MTOT];
__device__ float g_v    [MTOT];
__device__ float g_rs   [MTOT];

// ---------------- block reduction helper ------------------------------------
__device__ __forceinline__ float block_reduce_sum_256(float val, float* red) {
    int tid = threadIdx.x;
    #pragma unroll
    for (int o = 16; o > 0; o >>= 1) val += __shfl_down_sync(0xffffffffu, val, o);
    if ((tid & 31) == 0) red[tid >> 5] = val;
    __syncthreads();
    if (tid < 8) {
        val = red[tid];
        #pragma unroll
        for (int o = 4; o > 0; o >>= 1) val += __shfl_down_sync(0xffu, val, o);
        if (tid == 0) red[0] = val;
    }
    __syncthreads();
    float r = red[0];
    __syncthreads();
    return r;
}

#define BM 128
#define BN 128
#define BK 8

// micro-kernel: 8x8 outer product accumulate from smem buffers
#define MICRO_STEP(ASBUF, BSBUF, kk)                                           \
    {                                                                          \
        float4 a0 = *(const float4*)&ASBUF[kk][ty * 8];                        \
        float4 a1 = *(const float4*)&ASBUF[kk][ty * 8 + 4];                    \
        float4 b0 = *(const float4*)&BSBUF[kk][tx * 8];                        \
        float4 b1 = *(const float4*)&BSBUF[kk][tx * 8 + 4];                    \
        float ra[8] = {a0.x, a0.y, a0.z, a0.w, a1.x, a1.y, a1.z, a1.w};        \
        float rb[8] = {b0.x, b0.y, b0.z, b0.w, b1.x, b1.y, b1.z, b1.w};        \
        _Pragma("unroll")                                                      \
        for (int i = 0; i < 8; i++)                                            \
            _Pragma("unroll")                                                  \
            for (int j = 0; j < 8; j++) acc[i][j] += ra[i] * rb[j];            \
    }

// ---------------- GEMM: C[M,N] = A[M,K] @ W[K,N] + bias ----------------------
// 128x128 tile, BK=8, 256 threads, 8x8 per thread, double-buffered smem.
__global__ __launch_bounds__(256) void gemm_bias_kernel(
    const float* __restrict__ A, const float* __restrict__ W,
    const float* __restrict__ bias, float* __restrict__ C,
    int M, int N, int K)
{
    __shared__ float As[2][BK][BM];
    __shared__ float Bs[2][BK][BN];
    int tid = threadIdx.x;
    int bm = blockIdx.y * BM;
    int bn = blockIdx.x * BN;
    int tx = tid & 15, ty = tid >> 4;

    float acc[8][8];
    #pragma unroll
    for (int i = 0; i < 8; i++)
        #pragma unroll
        for (int j = 0; j < 8; j++) acc[i][j] = 0.f;

    int arow = tid >> 1, ak = (tid & 1) * 4;        // A loader: 128 rows x 8 k
    int bk  = tid >> 5, bn4 = (tid & 31) * 4;       // B loader: 8 k x 128 n
    const float* Aptr = A + (size_t)(bm + arow) * K + ak;
    const float* Wptr = W + (size_t)bk * N + bn + bn4;

    float4 av = *(const float4*)(Aptr);
    float4 bv = *(const float4*)(Wptr);
    As[0][ak + 0][arow] = av.x; As[0][ak + 1][arow] = av.y;
    As[0][ak + 2][arow] = av.z; As[0][ak + 3][arow] = av.w;
    *(float4*)&Bs[0][bk][bn4] = bv;
    __syncthreads();

    int buf = 0;
    for (int k0 = BK; k0 < K + BK; k0 += BK) {
        if (k0 < K) {
            av = *(const float4*)(Aptr + k0);
            bv = *(const float4*)(Wptr + (size_t)k0 * N);
        }
        #pragma unroll
        for (int kk = 0; kk < BK; kk++) MICRO_STEP(As[buf], Bs[buf], kk)
        if (k0 < K) {
            int nb = buf ^ 1;
            As[nb][ak + 0][arow] = av.x; As[nb][ak + 1][arow] = av.y;
            As[nb][ak + 2][arow] = av.z; As[nb][ak + 3][arow] = av.w;
            *(float4*)&Bs[nb][bk][bn4] = bv;
            __syncthreads();
            buf = nb;
        }
    }

    float4 bz0 = *(const float4*)&bias[bn + tx * 8];
    float4 bz1 = *(const float4*)&bias[bn + tx * 8 + 4];
    #pragma unroll
    for (int i = 0; i < 8; i++) {
        int row = bm + ty * 8 + i;
        float4 o0 = make_float4(acc[i][0] + bz0.x, acc[i][1] + bz0.y,
                                acc[i][2] + bz0.z, acc[i][3] + bz0.w);
        float4 o1 = make_float4(acc[i][4] + bz1.x, acc[i][5] + bz1.y,
                                acc[i][6] + bz1.z, acc[i][7] + bz1.w);
        *(float4*)&C[(size_t)row * N + bn + tx * 8]     = o0;
        *(float4*)&C[(size_t)row * N + bn + tx * 8 + 4] = o1;
    }
}

// ---------------- Q-GEMM (NT, batched): Q = exp(20 * cos_sim) ----------------
__global__ __launch_bounds__(256) void qgemm_kernel(
    const float* __restrict__ tar, const float* __restrict__ ofc,
    const float* __restrict__ itn, const float* __restrict__ ifn,
    float* __restrict__ Q)
{
    const int K = DH;
    int b = blockIdx.z;
    const float* A  = tar + (size_t)b * LL * DH;
    const float* Bm = ofc + (size_t)b * LL * DH;

    __shared__ float As[2][BK][BM];
    __shared__ float Bs[2][BK][BN];
    int tid = threadIdx.x;
    int bm = blockIdx.y * BM;
    int bn = blockIdx.x * BN;
    int tx = tid & 15, ty = tid >> 4;

    float acc[8][8];
    #pragma unroll
    for (int i = 0; i < 8; i++)
        #pragma unroll
        for (int j = 0; j < 8; j++) acc[i][j] = 0.f;

    int arow = tid >> 1, ak = (tid & 1) * 4;
    const float* Aptr = A  + (size_t)(bm + arow) * K + ak;
    const float* Bptr = Bm + (size_t)(bn + arow) * K + ak;

    float4 av = *(const float4*)(Aptr);
    float4 bv = *(const float4*)(Bptr);
    As[0][ak + 0][arow] = av.x; As[0][ak + 1][arow] = av.y;
    As[0][ak + 2][arow] = av.z; As[0][ak + 3][arow] = av.w;
    Bs[0][ak + 0][arow] = bv.x; Bs[0][ak + 1][arow] = bv.y;
    Bs[0][ak + 2][arow] = bv.z; Bs[0][ak + 3][arow] = bv.w;
    __syncthreads();

    int buf = 0;
    for (int k0 = BK; k0 < K + BK; k0 += BK) {
        if (k0 < K) {
            av = *(const float4*)(Aptr + k0);
            bv = *(const float4*)(Bptr + k0);
        }
        #pragma unroll
        for (int kk = 0; kk < BK; kk++) MICRO_STEP(As[buf], Bs[buf], kk)
        if (k0 < K) {
            int nb = buf ^ 1;
            As[nb][ak + 0][arow] = av.x; As[nb][ak + 1][arow] = av.y;
            As[nb][ak + 2][arow] = av.z; As[nb][ak + 3][arow] = av.w;
            Bs[nb][ak + 0][arow] = bv.x; Bs[nb][ak + 1][arow] = bv.y;
            Bs[nb][ak + 2][arow] = bv.z; Bs[nb][ak + 3][arow] = bv.w;
            __syncthreads();
            buf = nb;
        }
    }

    float fo[8];
    #pragma unroll
    for (int j = 0; j < 8; j++) fo[j] = ifn[b * LL + bn + tx * 8 + j];
    #pragma unroll
    for (int i = 0; i < 8; i++) {
        int t = bm + ty * 8 + i;
        float sc_t = itn[b * LL + t] * 20.0f;   // 1/OT_REG = 20
        float4 o0, o1;
        o0.x = expf(acc[i][0] * sc_t * fo[0]);
        o0.y = expf(acc[i][1] * sc_t * fo[1]);
        o0.z = expf(acc[i][2] * sc_t * fo[2]);
        o0.w = expf(acc[i][3] * sc_t * fo[3]);
        o1.x = expf(acc[i][4] * sc_t * fo[4]);
        o1.y = expf(acc[i][5] * sc_t * fo[5]);
        o1.z = expf(acc[i][6] * sc_t * fo[6]);
        o1.w = expf(acc[i][7] * sc_t * fo[7]);
        *(float4*)&Q[((size_t)b * LL + t) * LL + bn + tx * 8]     = o0;
        *(float4*)&Q[((size_t)b * LL + t) * LL + bn + tx * 8 + 4] = o1;
    }
}

// ---------------- Final GEMM (NN, batched): out = rs_t*(Q @ (v*otp)) + tar ---
__global__ __launch_bounds__(256) void fgemm_kernel(
    const float* __restrict__ Q, const float* __restrict__ otp,
    const float* __restrict__ v, const float* __restrict__ rs,
    const float* __restrict__ tar, float* __restrict__ out)
{
    const int K = LL;   // 512
    const int N = DH;
    int b = blockIdx.z;
    const float* A  = Q   + (size_t)b * LL * LL;
    const float* Bm = otp + (size_t)b * LL * DH;

    __shared__ float As[2][BK][BM];
    __shared__ float Bs[2][BK][BN];
    int tid = threadIdx.x;
    int bm = blockIdx.y * BM;
    int bn = blockIdx.x * BN;
    int tx = tid & 15, ty = tid >> 4;

    float acc[8][8];
    #pragma unroll
    for (int i = 0; i < 8; i++)
        #pragma unroll
        for (int j = 0; j < 8; j++) acc[i][j] = 0.f;

    int arow = tid >> 1, ak = (tid & 1) * 4;
    int bk  = tid >> 5, bn4 = (tid & 31) * 4;
    const float* Aptr = A  + (size_t)(bm + arow) * K + ak;
    const float* Bptr = Bm + (size_t)bk * N + bn + bn4;
    const float* vv   = v + b * LL;

    float4 av = *(const float4*)(Aptr);
    float4 bv = *(const float4*)(Bptr);
    float vs = vv[bk];
    As[0][ak + 0][arow] = av.x; As[0][ak + 1][arow] = av.y;
    As[0][ak + 2][arow] = av.z; As[0][ak + 3][arow] = av.w;
    bv.x *= vs; bv.y *= vs; bv.z *= vs; bv.w *= vs;
    *(float4*)&Bs[0][bk][bn4] = bv;
    __syncthreads();

    int buf = 0;
    for (int k0 = BK; k0 < K + BK; k0 += BK) {
        if (k0 < K) {
            av = *(const float4*)(Aptr + k0);
            bv = *(const float4*)(Bptr + (size_t)k0 * N);
            vs = vv[k0 + bk];
        }
        #pragma unroll
        for (int kk = 0; kk < BK; kk++) MICRO_STEP(As[buf], Bs[buf], kk)
        if (k0 < K) {
            int nb = buf ^ 1;
            As[nb][ak + 0][arow] = av.x; As[nb][ak + 1][arow] = av.y;
            As[nb][ak + 2][arow] = av.z; As[nb][ak + 3][arow] = av.w;
            bv.x *= vs; bv.y *= vs; bv.z *= vs; bv.w *= vs;
            *(float4*)&Bs[nb][bk][bn4] = bv;
            __syncthreads();
            buf = nb;
        }
    }

    #pragma unroll
    for (int i = 0; i < 8; i++) {
        int t = bm + ty * 8 + i;
        int grow = b * LL + t;
        float r = rs[grow];
        const float* tp = &tar[(size_t)grow * DH + bn + tx * 8];
        float4 t0v = *(const float4*)tp;
        float4 t1v = *(const float4*)(tp + 4);
        float4 o0 = make_float4(r * acc[i][0] + t0v.x, r * acc[i][1] + t0v.y,
                                r * acc[i][2] + t0v.z, r * acc[i][3] + t0v.w);
        float4 o1 = make_float4(r * acc[i][4] + t1v.x, r * acc[i][5] + t1v.y,
                                r * acc[i][6] + t1v.z, r * acc[i][7] + t1v.w);
        *(float4*)&out[(size_t)grow * DH + bn + tx * 8]     = o0;
        *(float4*)&out[(size_t)grow * DH + bn + tx * 8 + 4] = o1;
    }
}

// ---------------- row inverse-norm: inv[row] = 1/max(||x_row||, eps) ---------
__global__ __launch_bounds__(256) void row_invnorm_kernel(
    const float* __restrict__ x, float* __restrict__ inv, float eps)
{
    __shared__ float red[8];
    int row = blockIdx.x;
    const float* p = x + (size_t)row * DH;
    float s = 0.f;
    for (int c = threadIdx.x; c < DH; c += 256) { float v = p[c]; s += v * v; }
    float tot = block_reduce_sum_256(s, red);
    if (threadIdx.x == 0) inv[row] = 1.0f / fmaxf(sqrtf(tot), eps);
}

// ---------------- small vector kernels --------------------------------------
__global__ void set_ones_kernel(float* p, int n) {
    int i = blockIdx.x * blockDim.x + threadIdx.x;
    if (i < n) p[i] = 1.0f;
}

// u[b,t] = 1 / sum_o Q[b,t,o] * v[b,o]     (one warp per row)
__global__ void rowmv_kernel(const float* __restrict__ Q,
                             const float* __restrict__ v,
                             float* __restrict__ u)
{
    int t = blockIdx.x * 8 + threadIdx.y;
    int b = blockIdx.y;
    const float* row = Q + ((size_t)b * LL + t) * LL;
    const float* vv = v + b * LL;
    float s = 0.f;
    for (int o = threadIdx.x; o < LL; o += 32) s += row[o] * vv[o];
    #pragma unroll
    for (int off = 16; off > 0; off >>= 1) s += __shfl_down_sync(0xffffffffu, s, off);
    if (threadIdx.x == 0) u[b * LL + t] = 1.0f / s;
}

// v[b,o] = 1 / sum_t Q[b,t,o] * u[b,t]
__global__ void colmv_kernel(const float* __restrict__ Q,
                             const float* __restrict__ u,
                             float* __restrict__ v)
{
    __shared__ float red[8][32];
    int o = blockIdx.x * 32 + threadIdx.x;
    int b = blockIdx.y;
    const float* uu = u + b * LL;
    float s = 0.f;
    for (int t = threadIdx.y; t < LL; t += 8)
        s += Q[((size_t)b * LL + t) * LL + o] * uu[t];
    red[threadIdx.y][threadIdx.x] = s;
    __syncthreads();
    if (threadIdx.y == 0) {
        float tot = 0.f;
        #pragma unroll
        for (int j = 0; j < 8; j++) tot += red[j][threadIdx.x];
        v[b * LL + o] = 1.0f / tot;
    }
}

// rs[b,t] = u_t / max(u_t * sqrt(sum_o (Q_to * v_o)^2), 1e-12)
__global__ void rowscale_kernel(const float* __restrict__ Q,
                                const float* __restrict__ v,
                                const float* __restrict__ u,
                                float* __restrict__ rs)
{
    int t = blockIdx.x * 8 + threadIdx.y;
    int b = blockIdx.y;
    const float* row = Q + ((size_t)b * LL + t) * LL;
    const float* vv = v + b * LL;
    float s = 0.f;
    for (int o = threadIdx.x; o < LL; o += 32) {
        float q = row[o] * vv[o];
        s += q * q;
    }
    #pragma unroll
    for (int off = 16; off > 0; off >>= 1) s += __shfl_down_sync(0xffffffffu, s, off);
    if (threadIdx.x == 0) {
        float ut = u[b * LL + t];
        rs[b * LL + t] = ut / fmaxf(ut * sqrtf(s), 1e-12f);
    }
}

// ---------------- LayerNorm over last dim (1024) -----------------------------
__global__ __launch_bounds__(256) void ln_kernel(
    const float* __restrict__ x, const float* __restrict__ g,
    const float* __restrict__ beta, float* __restrict__ y)
{
    __shared__ float buf[DH];
    __shared__ float red[8];
    int row = blockIdx.x;
    const float* p = x + (size_t)row * DH;
    float s = 0.f;
    for (int c = threadIdx.x; c < DH; c += 256) { float v = p[c]; buf[c] = v; s += v; }
    float mean = block_reduce_sum_256(s, red) * (1.0f / DH);
    float s2 = 0.f;
    for (int c = threadIdx.x; c < DH; c += 256) { float d = buf[c] - mean; s2 += d * d; }
    float var = block_reduce_sum_256(s2, red) * (1.0f / DH);
    float inv = rsqrtf(var + 1e-5f);
    for (int c = threadIdx.x; c < DH; c += 256)
        y[(size_t)row * DH + c] = (buf[c] - mean) * inv * g[c] + beta[c];
}

// ---------------- launch -----------------------------------------------------
extern "C" void kernel_launch(void* const* d_in, const int* in_sizes, int n_in,
                              void* d_out, int out_size)
{
    const float* origin = (const float*)d_in[0];
    const float* target = (const float*)d_in[1];
    const float* W_ori = (const float*)d_in[2];  const float* b_ori = (const float*)d_in[3];
    const float* W_tar = (const float*)d_in[4];  const float* b_tar = (const float*)d_in[5];
    const float* W_ft  = (const float*)d_in[6];  const float* b_ft  = (const float*)d_in[7];
    const float* W_fo  = (const float*)d_in[8];  const float* b_fo  = (const float*)d_in[9];
    const float* W_fot = (const float*)d_in[10]; const float* b_fot = (const float*)d_in[11];
    const float* ln_g  = (const float*)d_in[12]; const float* ln_b  = (const float*)d_in[13];
    float* out = (float*)d_out;

    float *ori, *t0, *tar, *ofc, *otp, *obuf, *Q, *itn, *ifn, *u, *v, *rs;
    cudaGetSymbolAddress((void**)&ori,  g_ori);
    cudaGetSymbolAddress((void**)&t0,   g_t0);
    cudaGetSymbolAddress((void**)&tar,  g_tar);
    cudaGetSymbolAddress((void**)&ofc,  g_ofc);
    cudaGetSymbolAddress((void**)&otp,  g_otp);
    cudaGetSymbolAddress((void**)&obuf, g_obuf);
    cudaGetSymbolAddress((void**)&Q,    g_Q);
    cudaGetSymbolAddress((void**)&itn,  g_itn);
    cudaGetSymbolAddress((void**)&ifn,  g_ifn);
    cudaGetSymbolAddress((void**)&u,    g_u);
    cudaGetSymbolAddress((void**)&v,    g_v);
    cudaGetSymbolAddress((void**)&rs,   g_rs);

    dim3 blk(256);
    dim3 gBig(DH / BN, MTOT / BM);          // 8 x 64

    // 5 dense GEMMs
    gemm_bias_kernel<<<gBig, blk>>>(origin, W_ori, b_ori, ori, MTOT, DH, DIN);
    gemm_bias_kernel<<<gBig, blk>>>(target, W_tar, b_tar, t0,  MTOT, DH, DIN);
    gemm_bias_kernel<<<gBig, blk>>>(t0,     W_ft,  b_ft,  tar, MTOT, DH, DH);
    gemm_bias_kernel<<<gBig, blk>>>(ori,    W_fo,  b_fo,  ofc, MTOT, DH, DH);
    gemm_bias_kernel<<<gBig, blk>>>(ori,    W_fot, b_fot, otp, MTOT, DH, DH);

    // row inverse norms for cosine similarity
    row_invnorm_kernel<<<MTOT, blk>>>(tar, itn, 1e-8f);
    row_invnorm_kernel<<<MTOT, blk>>>(ofc, ifn, 1e-8f);

    // Q = exp(cos/0.05)
    qgemm_kernel<<<dim3(LL / BN, LL / BM, BB), blk>>>(tar, ofc, itn, ifn, Q);

    // Sinkhorn via scaling vectors: u = 1/(Qv), v = 1/(Q^T u), 5 iterations
    set_ones_kernel<<<(MTOT + 255) / 256, 256>>>(v, MTOT);
    for (int it = 0; it < 5; it++) {
        rowmv_kernel<<<dim3(LL / 8, BB), dim3(32, 8)>>>(Q, v, u);
        colmv_kernel<<<dim3(LL / 32, BB), dim3(32, 8)>>>(Q, u, v);
    }
    // per-row normalize scale for plan = l2norm(diag(u) Q diag(v), dim=-1)
    rowscale_kernel<<<dim3(LL / 8, BB), dim3(32, 8)>>>(Q, v, u, rs);

    // out = rs_t * (Q @ (v .* otp)) + tar
    fgemm_kernel<<<dim3(DH / BN, LL / BM, BB), blk>>>(Q, otp, v, rs, tar, obuf);

    // LayerNorm
    ln_kernel<<<MTOT, blk>>>(obuf, ln_g, ln_b, out);
}

// round 3
// speedup vs baseline: 1.7302x; 1.6147x over previous
#include <cuda_runtime.h>
#include <math.h>

// Problem dims (fixed by the dataset)
#define BB   16
#define LL   512
#define DIN  1024
#define DH   1024
#define MTOT (BB * LL)   // 8192

// ---------------- scratch (static __device__: allocation-free) --------------
__device__ float g_ori  [(size_t)MTOT * DH];
__device__ float g_t0   [(size_t)MTOT * DH];
__device__ float g_tar  [(size_t)MTOT * DH];
__device__ float g_ofc  [(size_t)MTOT * DH];
__device__ float g_otp  [(size_t)MTOT * DH];
__device__ float g_obuf [(size_t)MTOT * DH];
__device__ float g_Q    [(size_t)BB * LL * LL];
__device__ float g_itn  [MTOT];
__device__ float g_ifn  [MTOT];
__device__ float g_u    [MTOT];
__device__ float g_v    [MTOT];
__device__ float g_rs   [MTOT];

// ---------------- packed f32x2 helpers (Blackwell FFMA2) ---------------------
__device__ __forceinline__ unsigned long long pack_dup(float a) {
    unsigned long long r;
    asm("mov.b64 %0, {%1, %1};" : "=l"(r) : "f"(a));
    return r;
}
__device__ __forceinline__ void fma2(unsigned long long& d,
                                     unsigned long long a,
                                     unsigned long long b) {
    asm("fma.rn.f32x2 %0, %1, %2, %0;" : "+l"(d) : "l"(a), "l"(b));
}
__device__ __forceinline__ float2 unpack2(unsigned long long p) {
    float2 v;
    asm("mov.b64 {%0, %1}, %2;" : "=f"(v.x), "=f"(v.y) : "l"(p));
    return v;
}

// ---------------- block reduction helper ------------------------------------
__device__ __forceinline__ float block_reduce_sum_256(float val, float* red) {
    int tid = threadIdx.x;
    #pragma unroll
    for (int o = 16; o > 0; o >>= 1) val += __shfl_down_sync(0xffffffffu, val, o);
    if ((tid & 31) == 0) red[tid >> 5] = val;
    __syncthreads();
    if (tid < 8) {
        val = red[tid];
        #pragma unroll
        for (int o = 4; o > 0; o >>= 1) val += __shfl_down_sync(0xffu, val, o);
        if (tid == 0) red[0] = val;
    }
    __syncthreads();
    float r = red[0];
    __syncthreads();
    return r;
}

#define BM 128
#define BN 128
#define BK 8

// micro-kernel: 8 rows x 4 col-pairs outer product with packed FFMA2
#define MICRO_STEP2(ASBUF, BSBUF, kk)                                          \
    {                                                                          \
        float4 a0 = *(const float4*)&ASBUF[kk][ty * 8];                        \
        float4 a1 = *(const float4*)&ASBUF[kk][ty * 8 + 4];                    \
        ulonglong2 b0 = *(const ulonglong2*)&BSBUF[kk][tx * 8];                \
        ulonglong2 b1 = *(const ulonglong2*)&BSBUF[kk][tx * 8 + 4];            \
        unsigned long long rb2[4] = {b0.x, b0.y, b1.x, b1.y};                  \
        float ra[8] = {a0.x, a0.y, a0.z, a0.w, a1.x, a1.y, a1.z, a1.w};        \
        _Pragma("unroll")                                                      \
        for (int i = 0; i < 8; i++) {                                          \
            unsigned long long pa = pack_dup(ra[i]);                           \
            _Pragma("unroll")                                                  \
            for (int j = 0; j < 4; j++) fma2(acc2[i][j], pa, rb2[j]);          \
        }                                                                      \
    }

// ---------------- GEMM: C[M,N] = A[M,K] @ W[K,N] + bias ----------------------
// 128x128 tile, BK=8, 256 threads, 8x8 per thread, double-buffered smem,
// packed f32x2 accumulation.
__global__ __launch_bounds__(256) void gemm_bias_kernel(
    const float* __restrict__ A, const float* __restrict__ W,
    const float* __restrict__ bias, float* __restrict__ C,
    int M, int N, int K)
{
    __shared__ float As[2][BK][BM];
    __shared__ float Bs[2][BK][BN];
    int tid = threadIdx.x;
    int bm = blockIdx.y * BM;
    int bn = blockIdx.x * BN;
    int tx = tid & 15, ty = tid >> 4;

    unsigned long long acc2[8][4];
    #pragma unroll
    for (int i = 0; i < 8; i++)
        #pragma unroll
        for (int j = 0; j < 4; j++) acc2[i][j] = 0ull;

    int arow = tid >> 1, ak = (tid & 1) * 4;        // A loader: 128 rows x 8 k
    int bk  = tid >> 5, bn4 = (tid & 31) * 4;       // B loader: 8 k x 128 n
    const float* Aptr = A + (size_t)(bm + arow) * K + ak;
    const float* Wptr = W + (size_t)bk * N + bn + bn4;

    float4 av = *(const float4*)(Aptr);
    float4 bv = *(const float4*)(Wptr);
    As[0][ak + 0][arow] = av.x; As[0][ak + 1][arow] = av.y;
    As[0][ak + 2][arow] = av.z; As[0][ak + 3][arow] = av.w;
    *(float4*)&Bs[0][bk][bn4] = bv;
    __syncthreads();

    int buf = 0;
    for (int k0 = BK; k0 < K + BK; k0 += BK) {
        if (k0 < K) {
            av = *(const float4*)(Aptr + k0);
            bv = *(const float4*)(Wptr + (size_t)k0 * N);
        }
        #pragma unroll
        for (int kk = 0; kk < BK; kk++) MICRO_STEP2(As[buf], Bs[buf], kk)
        if (k0 < K) {
            int nb = buf ^ 1;
            As[nb][ak + 0][arow] = av.x; As[nb][ak + 1][arow] = av.y;
            As[nb][ak + 2][arow] = av.z; As[nb][ak + 3][arow] = av.w;
            *(float4*)&Bs[nb][bk][bn4] = bv;
            __syncthreads();
            buf = nb;
        }
    }

    float4 bz0 = *(const float4*)&bias[bn + tx * 8];
    float4 bz1 = *(const float4*)&bias[bn + tx * 8 + 4];
    #pragma unroll
    for (int i = 0; i < 8; i++) {
        int row = bm + ty * 8 + i;
        float2 p0 = unpack2(acc2[i][0]);
        float2 p1 = unpack2(acc2[i][1]);
        float2 p2 = unpack2(acc2[i][2]);
        float2 p3 = unpack2(acc2[i][3]);
        float4 o0 = make_float4(p0.x + bz0.x, p0.y + bz0.y,
                                p1.x + bz0.z, p1.y + bz0.w);
        float4 o1 = make_float4(p2.x + bz1.x, p2.y + bz1.y,
                                p3.x + bz1.z, p3.y + bz1.w);
        *(float4*)&C[(size_t)row * N + bn + tx * 8]     = o0;
        *(float4*)&C[(size_t)row * N + bn + tx * 8 + 4] = o1;
    }
}

// ---------------- Q-GEMM (NT, batched): Q = exp(20 * cos_sim) ----------------
__global__ __launch_bounds__(256) void qgemm_kernel(
    const float* __restrict__ tar, const float* __restrict__ ofc,
    const float* __restrict__ itn, const float* __restrict__ ifn,
    float* __restrict__ Q)
{
    const int K = DH;
    int b = blockIdx.z;
    const float* A  = tar + (size_t)b * LL * DH;
    const float* Bm = ofc + (size_t)b * LL * DH;

    __shared__ float As[2][BK][BM];
    __shared__ float Bs[2][BK][BN];
    int tid = threadIdx.x;
    int bm = blockIdx.y * BM;
    int bn = blockIdx.x * BN;
    int tx = tid & 15, ty = tid >> 4;

    unsigned long long acc2[8][4];
    #pragma unroll
    for (int i = 0; i < 8; i++)
        #pragma unroll
        for (int j = 0; j < 4; j++) acc2[i][j] = 0ull;

    int arow = tid >> 1, ak = (tid & 1) * 4;
    const float* Aptr = A  + (size_t)(bm + arow) * K + ak;
    const float* Bptr = Bm + (size_t)(bn + arow) * K + ak;

    float4 av = *(const float4*)(Aptr);
    float4 bv = *(const float4*)(Bptr);
    As[0][ak + 0][arow] = av.x; As[0][ak + 1][arow] = av.y;
    As[0][ak + 2][arow] = av.z; As[0][ak + 3][arow] = av.w;
    Bs[0][ak + 0][arow] = bv.x; Bs[0][ak + 1][arow] = bv.y;
    Bs[0][ak + 2][arow] = bv.z; Bs[0][ak + 3][arow] = bv.w;
    __syncthreads();

    int buf = 0;
    for (int k0 = BK; k0 < K + BK; k0 += BK) {
        if (k0 < K) {
            av = *(const float4*)(Aptr + k0);
            bv = *(const float4*)(Bptr + k0);
        }
        #pragma unroll
        for (int kk = 0; kk < BK; kk++) MICRO_STEP2(As[buf], Bs[buf], kk)
        if (k0 < K) {
            int nb = buf ^ 1;
            As[nb][ak + 0][arow] = av.x; As[nb][ak + 1][arow] = av.y;
            As[nb][ak + 2][arow] = av.z; As[nb][ak + 3][arow] = av.w;
            Bs[nb][ak + 0][arow] = bv.x; Bs[nb][ak + 1][arow] = bv.y;
            Bs[nb][ak + 2][arow] = bv.z; Bs[nb][ak + 3][arow] = bv.w;
            __syncthreads();
            buf = nb;
        }
    }

    float fo[8];
    #pragma unroll
    for (int j = 0; j < 8; j++) fo[j] = ifn[b * LL + bn + tx * 8 + j];
    #pragma unroll
    for (int i = 0; i < 8; i++) {
        int t = bm + ty * 8 + i;
        float sc_t = itn[b * LL + t] * 20.0f;   // 1/OT_REG = 20
        float2 p0 = unpack2(acc2[i][0]);
        float2 p1 = unpack2(acc2[i][1]);
        float2 p2 = unpack2(acc2[i][2]);
        float2 p3 = unpack2(acc2[i][3]);
        float4 o0, o1;
        o0.x = expf(p0.x * sc_t * fo[0]);
        o0.y = expf(p0.y * sc_t * fo[1]);
        o0.z = expf(p1.x * sc_t * fo[2]);
        o0.w = expf(p1.y * sc_t * fo[3]);
        o1.x = expf(p2.x * sc_t * fo[4]);
        o1.y = expf(p2.y * sc_t * fo[5]);
        o1.z = expf(p3.x * sc_t * fo[6]);
        o1.w = expf(p3.y * sc_t * fo[7]);
        *(float4*)&Q[((size_t)b * LL + t) * LL + bn + tx * 8]     = o0;
        *(float4*)&Q[((size_t)b * LL + t) * LL + bn + tx * 8 + 4] = o1;
    }
}

// ---------------- Final GEMM (NN, batched): out = rs_t*(Q @ (v*otp)) + tar ---
__global__ __launch_bounds__(256) void fgemm_kernel(
    const float* __restrict__ Q, const float* __restrict__ otp,
    const float* __restrict__ v, const float* __restrict__ rs,
    const float* __restrict__ tar, float* __restrict__ out)
{
    const int K = LL;   // 512
    const int N = DH;
    int b = blockIdx.z;
    const float* A  = Q   + (size_t)b * LL * LL;
    const float* Bm = otp + (size_t)b * LL * DH;

    __shared__ float As[2][BK][BM];
    __shared__ float Bs[2][BK][BN];
    int tid = threadIdx.x;
    int bm = blockIdx.y * BM;
    int bn = blockIdx.x * BN;
    int tx = tid & 15, ty = tid >> 4;

    unsigned long long acc2[8][4];
    #pragma unroll
    for (int i = 0; i < 8; i++)
        #pragma unroll
        for (int j = 0; j < 4; j++) acc2[i][j] = 0ull;

    int arow = tid >> 1, ak = (tid & 1) * 4;
    int bk  = tid >> 5, bn4 = (tid & 31) * 4;
    const float* Aptr = A  + (size_t)(bm + arow) * K + ak;
    const float* Bptr = Bm + (size_t)bk * N + bn + bn4;
    const float* vv   = v + b * LL;

    float4 av = *(const float4*)(Aptr);
    float4 bv = *(const float4*)(Bptr);
    float vs = vv[bk];
    As[0][ak + 0][arow] = av.x; As[0][ak + 1][arow] = av.y;
    As[0][ak + 2][arow] = av.z; As[0][ak + 3][arow] = av.w;
    bv.x *= vs; bv.y *= vs; bv.z *= vs; bv.w *= vs;
    *(float4*)&Bs[0][bk][bn4] = bv;
    __syncthreads();

    int buf = 0;
    for (int k0 = BK; k0 < K + BK; k0 += BK) {
        if (k0 < K) {
            av = *(const float4*)(Aptr + k0);
            bv = *(const float4*)(Bptr + (size_t)k0 * N);
            vs = vv[k0 + bk];
        }
        #pragma unroll
        for (int kk = 0; kk < BK; kk++) MICRO_STEP2(As[buf], Bs[buf], kk)
        if (k0 < K) {
            int nb = buf ^ 1;
            As[nb][ak + 0][arow] = av.x; As[nb][ak + 1][arow] = av.y;
            As[nb][ak + 2][arow] = av.z; As[nb][ak + 3][arow] = av.w;
            bv.x *= vs; bv.y *= vs; bv.z *= vs; bv.w *= vs;
            *(float4*)&Bs[nb][bk][bn4] = bv;
            __syncthreads();
            buf = nb;
        }
    }

    #pragma unroll
    for (int i = 0; i < 8; i++) {
        int t = bm + ty * 8 + i;
        int grow = b * LL + t;
        float r = rs[grow];
        const float* tp = &tar[(size_t)grow * DH + bn + tx * 8];
        float4 t0v = *(const float4*)tp;
        float4 t1v = *(const float4*)(tp + 4);
        float2 p0 = unpack2(acc2[i][0]);
        float2 p1 = unpack2(acc2[i][1]);
        float2 p2 = unpack2(acc2[i][2]);
        float2 p3 = unpack2(acc2[i][3]);
        float4 o0 = make_float4(r * p0.x + t0v.x, r * p0.y + t0v.y,
                                r * p1.x + t0v.z, r * p1.y + t0v.w);
        float4 o1 = make_float4(r * p2.x + t1v.x, r * p2.y + t1v.y,
                                r * p3.x + t1v.z, r * p3.y + t1v.w);
        *(float4*)&out[(size_t)grow * DH + bn + tx * 8]     = o0;
        *(float4*)&out[(size_t)grow * DH + bn + tx * 8 + 4] = o1;
    }
}

// ---------------- row inverse-norm: inv[row] = 1/max(||x_row||, eps) ---------
__global__ __launch_bounds__(256) void row_invnorm_kernel(
    const float* __restrict__ x, float* __restrict__ inv, float eps)
{
    __shared__ float red[8];
    int row = blockIdx.x;
    const float* p = x + (size_t)row * DH;
    float s = 0.f;
    for (int c = threadIdx.x; c < DH; c += 256) { float v = p[c]; s += v * v; }
    float tot = block_reduce_sum_256(s, red);
    if (threadIdx.x == 0) inv[row] = 1.0f / fmaxf(sqrtf(tot), eps);
}

// ---------------- small vector kernels --------------------------------------
__global__ void set_ones_kernel(float* p, int n) {
    int i = blockIdx.x * blockDim.x + threadIdx.x;
    if (i < n) p[i] = 1.0f;
}

// u[b,t] = 1 / sum_o Q[b,t,o] * v[b,o]     (one warp per row)
__global__ void rowmv_kernel(const float* __restrict__ Q,
                             const float* __restrict__ v,
                             float* __restrict__ u)
{
    int t = blockIdx.x * 8 + threadIdx.y;
    int b = blockIdx.y;
    const float* row = Q + ((size_t)b * LL + t) * LL;
    const float* vv = v + b * LL;
    float s = 0.f;
    for (int o = threadIdx.x; o < LL; o += 32) s += row[o] * vv[o];
    #pragma unroll
    for (int off = 16; off > 0; off >>= 1) s += __shfl_down_sync(0xffffffffu, s, off);
    if (threadIdx.x == 0) u[b * LL + t] = 1.0f / s;
}

// v[b,o] = 1 / sum_t Q[b,t,o] * u[b,t]
__global__ void colmv_kernel(const float* __restrict__ Q,
                             const float* __restrict__ u,
                             float* __restrict__ v)
{
    __shared__ float red[8][32];
    int o = blockIdx.x * 32 + threadIdx.x;
    int b = blockIdx.y;
    const float* uu = u + b * LL;
    float s = 0.f;
    for (int t = threadIdx.y; t < LL; t += 8)
        s += Q[((size_t)b * LL + t) * LL + o] * uu[t];
    red[threadIdx.y][threadIdx.x] = s;
    __syncthreads();
    if (threadIdx.y == 0) {
        float tot = 0.f;
        #pragma unroll
        for (int j = 0; j < 8; j++) tot += red[j][threadIdx.x];
        v[b * LL + o] = 1.0f / tot;
    }
}

// rs[b,t] = u_t / max(u_t * sqrt(sum_o (Q_to * v_o)^2), 1e-12)
__global__ void rowscale_kernel(const float* __restrict__ Q,
                                const float* __restrict__ v,
                                const float* __restrict__ u,
                                float* __restrict__ rs)
{
    int t = blockIdx.x * 8 + threadIdx.y;
    int b = blockIdx.y;
    const float* row = Q + ((size_t)b * LL + t) * LL;
    const float* vv = v + b * LL;
    float s = 0.f;
    for (int o = threadIdx.x; o < LL; o += 32) {
        float q = row[o] * vv[o];
        s += q * q;
    }
    #pragma unroll
    for (int off = 16; off > 0; off >>= 1) s += __shfl_down_sync(0xffffffffu, s, off);
    if (threadIdx.x == 0) {
        float ut = u[b * LL + t];
        rs[b * LL + t] = ut / fmaxf(ut * sqrtf(s), 1e-12f);
    }
}

// ---------------- LayerNorm over last dim (1024) -----------------------------
__global__ __launch_bounds__(256) void ln_kernel(
    const float* __restrict__ x, const float* __restrict__ g,
    const float* __restrict__ beta, float* __restrict__ y)
{
    __shared__ float buf[DH];
    __shared__ float red[8];
    int row = blockIdx.x;
    const float* p = x + (size_t)row * DH;
    float s = 0.f;
    for (int c = threadIdx.x; c < DH; c += 256) { float v = p[c]; buf[c] = v; s += v; }
    float mean = block_reduce_sum_256(s, red) * (1.0f / DH);
    float s2 = 0.f;
    for (int c = threadIdx.x; c < DH; c += 256) { float d = buf[c] - mean; s2 += d * d; }
    float var = block_reduce_sum_256(s2, red) * (1.0f / DH);
    float inv = rsqrtf(var + 1e-5f);
    for (int c = threadIdx.x; c < DH; c += 256)
        y[(size_t)row * DH + c] = (buf[c] - mean) * inv * g[c] + beta[c];
}

// ---------------- launch -----------------------------------------------------
extern "C" void kernel_launch(void* const* d_in, const int* in_sizes, int n_in,
                              void* d_out, int out_size)
{
    const float* origin = (const float*)d_in[0];
    const float* target = (const float*)d_in[1];
    const float* W_ori = (const float*)d_in[2];  const float* b_ori = (const float*)d_in[3];
    const float* W_tar = (const float*)d_in[4];  const float* b_tar = (const float*)d_in[5];
    const float* W_ft  = (const float*)d_in[6];  const float* b_ft  = (const float*)d_in[7];
    const float* W_fo  = (const float*)d_in[8];  const float* b_fo  = (const float*)d_in[9];
    const float* W_fot = (const float*)d_in[10]; const float* b_fot = (const float*)d_in[11];
    const float* ln_g  = (const float*)d_in[12]; const float* ln_b  = (const float*)d_in[13];
    float* out = (float*)d_out;

    float *ori, *t0, *tar, *ofc, *otp, *obuf, *Q, *itn, *ifn, *u, *v, *rs;
    cudaGetSymbolAddress((void**)&ori,  g_ori);
    cudaGetSymbolAddress((void**)&t0,   g_t0);
    cudaGetSymbolAddress((void**)&tar,  g_tar);
    cudaGetSymbolAddress((void**)&ofc,  g_ofc);
    cudaGetSymbolAddress((void**)&otp,  g_otp);
    cudaGetSymbolAddress((void**)&obuf, g_obuf);
    cudaGetSymbolAddress((void**)&Q,    g_Q);
    cudaGetSymbolAddress((void**)&itn,  g_itn);
    cudaGetSymbolAddress((void**)&ifn,  g_ifn);
    cudaGetSymbolAddress((void**)&u,    g_u);
    cudaGetSymbolAddress((void**)&v,    g_v);
    cudaGetSymbolAddress((void**)&rs,   g_rs);

    dim3 blk(256);
    dim3 gBig(DH / BN, MTOT / BM);          // 8 x 64

    // 5 dense GEMMs
    gemm_bias_kernel<<<gBig, blk>>>(origin, W_ori, b_ori, ori, MTOT, DH, DIN);
    gemm_bias_kernel<<<gBig, blk>>>(target, W_tar, b_tar, t0,  MTOT, DH, DIN);
    gemm_bias_kernel<<<gBig, blk>>>(t0,     W_ft,  b_ft,  tar, MTOT, DH, DH);
    gemm_bias_kernel<<<gBig, blk>>>(ori,    W_fo,  b_fo,  ofc, MTOT, DH, DH);
    gemm_bias_kernel<<<gBig, blk>>>(ori,    W_fot, b_fot, otp, MTOT, DH, DH);

    // row inverse norms for cosine similarity
    row_invnorm_kernel<<<MTOT, blk>>>(tar, itn, 1e-8f);
    row_invnorm_kernel<<<MTOT, blk>>>(ofc, ifn, 1e-8f);

    // Q = exp(cos/0.05)
    qgemm_kernel<<<dim3(LL / BN, LL / BM, BB), blk>>>(tar, ofc, itn, ifn, Q);

    // Sinkhorn via scaling vectors: u = 1/(Qv), v = 1/(Q^T u), 5 iterations
    set_ones_kernel<<<(MTOT + 255) / 256, 256>>>(v, MTOT);
    for (int it = 0; it < 5; it++) {
        rowmv_kernel<<<dim3(LL / 8, BB), dim3(32, 8)>>>(Q, v, u);
        colmv_kernel<<<dim3(LL / 32, BB), dim3(32, 8)>>>(Q, u, v);
    }
    // per-row normalize scale for plan = l2norm(diag(u) Q diag(v), dim=-1)
    rowscale_kernel<<<dim3(LL / 8, BB), dim3(32, 8)>>>(Q, v, u, rs);

    // out = rs_t * (Q @ (v .* otp)) + tar
    fgemm_kernel<<<dim3(DH / BN, LL / BM, BB), blk>>>(Q, otp, v, rs, tar, obuf);

    // LayerNorm
    ln_kernel<<<MTOT, blk>>>(obuf, ln_g, ln_b, out);
}

// round 5
// speedup vs baseline: 2.5115x; 1.4516x over previous
#include <cuda_runtime.h>
#include <cuda_bf16.h>
#include <math.h>
#include <stdint.h>

// Problem dims (fixed by the dataset)
#define BB   16
#define LL   512
#define DIN  1024
#define DH   1024
#define MTOT (BB * LL)   // 8192

// ---------------- scratch (static __device__: allocation-free) --------------
__device__ __nv_bfloat16 g_ohi [(size_t)MTOT * DH];
__device__ __nv_bfloat16 g_olo [(size_t)MTOT * DH];
__device__ __nv_bfloat16 g_thi [(size_t)MTOT * DH];
__device__ __nv_bfloat16 g_tlo [(size_t)MTOT * DH];
__device__ __nv_bfloat16 g_orihi[(size_t)MTOT * DH];
__device__ __nv_bfloat16 g_orilo[(size_t)MTOT * DH];
__device__ __nv_bfloat16 g_t0hi[(size_t)MTOT * DH];
__device__ __nv_bfloat16 g_t0lo[(size_t)MTOT * DH];
__device__ __nv_bfloat16 g_wthi[(size_t)5 * DH * DH];
__device__ __nv_bfloat16 g_wtlo[(size_t)5 * DH * DH];
__device__ float g_tar  [(size_t)MTOT * DH];
__device__ float g_ofc  [(size_t)MTOT * DH];
__device__ float g_otp  [(size_t)MTOT * DH];
__device__ float g_obuf [(size_t)MTOT * DH];
__device__ float g_Q    [(size_t)BB * LL * LL];
__device__ float g_itn  [MTOT];
__device__ float g_ifn  [MTOT];
__device__ float g_u    [MTOT];
__device__ float g_v    [MTOT];
__device__ float g_rs   [MTOT];

// ================= portable tensor-core helpers (sm_80 PTX) ==================
__device__ __forceinline__ uint32_t smem_u32(const void* p) {
    uint32_t a;
    asm("{ .reg .u64 t; cvta.to.shared.u64 t, %1; cvt.u32.u64 %0, t; }"
        : "=r"(a) : "l"(p));
    return a;
}
__device__ __forceinline__ void cp16(uint32_t s, const void* g) {
    asm volatile("cp.async.cg.shared.global [%0], [%1], 16;"
                 :: "r"(s), "l"(g) : "memory");
}
#define CP_COMMIT() asm volatile("cp.async.commit_group;" ::: "memory")
#define CP_WAIT(n)  asm volatile("cp.async.wait_group %0;" :: "n"(n) : "memory")

__device__ __forceinline__ void ldmx4(uint32_t* r, uint32_t addr) {
    asm volatile("ldmatrix.sync.aligned.m8n8.x4.shared.b16 {%0,%1,%2,%3}, [%4];"
        : "=r"(r[0]), "=r"(r[1]), "=r"(r[2]), "=r"(r[3]) : "r"(addr));
}
__device__ __forceinline__ void mma_bf16(float* d, const uint32_t* a,
                                         uint32_t b0, uint32_t b1) {
    asm volatile(
        "mma.sync.aligned.m16n8k16.row.col.f32.bf16.bf16.f32 "
        "{%0,%1,%2,%3}, {%4,%5,%6,%7}, {%8,%9}, {%0,%1,%2,%3};"
        : "+f"(d[0]), "+f"(d[1]), "+f"(d[2]), "+f"(d[3])
        : "r"(a[0]), "r"(a[1]), "r"(a[2]), "r"(a[3]), "r"(b0), "r"(b1));
}

// ================= bf16-split tensor-core GEMM ===============================
// D[M,N] = (Ahi+Alo) @ (Bhi+Blo)^T + bias  (3-term: hh + h*lo + lo*h)
// A*, B* are [rows,1024] K-major bf16.  CTA tile 128x128, warp 64x32,
// K-chunk 32, cp.async double-buffered, ldmatrix fragments.
#define NCH 96   // 3 segments x 32 chunks

__global__ __launch_bounds__(256) void gemm_tc_kernel(
    const __nv_bfloat16* __restrict__ Ahi, const __nv_bfloat16* __restrict__ Alo,
    const __nv_bfloat16* __restrict__ Bhi, const __nv_bfloat16* __restrict__ Blo,
    const float* __restrict__ bias,
    float* __restrict__ outF,
    __nv_bfloat16* __restrict__ outHi, __nv_bfloat16* __restrict__ outLo)
{
    __shared__ __align__(16) __nv_bfloat16 As[2][128][40];
    __shared__ __align__(16) __nv_bfloat16 Bs[2][128][40];

    const int K = 1024;
    int tid = threadIdx.x;
    int lane = tid & 31, wid = tid >> 5;
    int warp_m = wid >> 2, warp_n = wid & 3;     // 2 x 4 warp grid
    int m0 = blockIdx.y * 128, n0 = blockIdx.x * 128;

    // cp.async mapping: row = tid/2, two 16B chunks per thread
    int prow = tid >> 1;
    int pc0 = (tid & 1) * 2;

    uint32_t sA[2] = { smem_u32(&As[0][0][0]), smem_u32(&As[1][0][0]) };
    uint32_t sB[2] = { smem_u32(&Bs[0][0][0]), smem_u32(&Bs[1][0][0]) };

    auto prefetch = [&](int kc, int b) {
        int seg = kc >> 5;
        int ko = (kc & 31) << 5;
        const __nv_bfloat16* Asrc = (seg == 2) ? Alo : Ahi;
        const __nv_bfloat16* Bsrc = (seg == 1) ? Blo : Bhi;
        const __nv_bfloat16* ag = Asrc + (size_t)(m0 + prow) * K + ko;
        const __nv_bfloat16* bg = Bsrc + (size_t)(n0 + prow) * K + ko;
        uint32_t sa = sA[b] + prow * 80;
        uint32_t sb = sB[b] + prow * 80;
        #pragma unroll
        for (int j = 0; j < 2; j++) {
            int c = pc0 + j;
            cp16(sa + c * 16, ag + c * 8);
            cp16(sb + c * 16, bg + c * 8);
        }
        CP_COMMIT();
    };

    // ldmatrix per-thread base offsets
    int mat = lane >> 3, mr = lane & 7;
    uint32_t aoff = (uint32_t)((warp_m * 64 + (mat & 1) * 8 + mr) * 80
                               + ((mat >> 1) * 8) * 2);
    uint32_t boff = (uint32_t)((warp_n * 32 + (mat >> 1) * 8 + mr) * 80
                               + ((mat & 1) * 8) * 2);

    float acc[4][4][4];
    #pragma unroll
    for (int mi = 0; mi < 4; mi++)
        #pragma unroll
        for (int ni = 0; ni < 4; ni++)
            #pragma unroll
            for (int e = 0; e < 4; e++) acc[mi][ni][e] = 0.f;

    prefetch(0, 0);
    prefetch(1, 1);

    for (int kc = 0; kc < NCH; kc++) {
        if (kc == NCH - 1) { CP_WAIT(0); } else { CP_WAIT(1); }
        __syncthreads();
        int b = kc & 1;
        #pragma unroll
        for (int ks = 0; ks < 32; ks += 16) {
            uint32_t afr[4][4];
            #pragma unroll
            for (int mi = 0; mi < 4; mi++)
                ldmx4(afr[mi], sA[b] + aoff + mi * (16 * 80) + ks * 2);
            uint32_t bfr[2][4];
            #pragma unroll
            for (int np = 0; np < 2; np++)
                ldmx4(bfr[np], sB[b] + boff + np * (16 * 80) + ks * 2);
            #pragma unroll
            for (int mi = 0; mi < 4; mi++)
                #pragma unroll
                for (int ni = 0; ni < 4; ni++)
                    mma_bf16(acc[mi][ni], afr[mi],
                             bfr[ni >> 1][(ni & 1) * 2],
                             bfr[ni >> 1][(ni & 1) * 2 + 1]);
        }
        __syncthreads();
        if (kc + 2 < NCH) prefetch(kc + 2, b);
    }

    // epilogue
    int gid = lane >> 2, tig = lane & 3;
    #pragma unroll
    for (int ni = 0; ni < 4; ni++) {
        int cn = n0 + warp_n * 32 + ni * 8 + tig * 2;
        float bz0 = bias[cn], bz1 = bias[cn + 1];
        #pragma unroll
        for (int mi = 0; mi < 4; mi++) {
            int rm = m0 + warp_m * 64 + mi * 16 + gid;
            float c0 = acc[mi][ni][0] + bz0, c1 = acc[mi][ni][1] + bz1;
            float c2 = acc[mi][ni][2] + bz0, c3 = acc[mi][ni][3] + bz1;
            if (outF) {
                *(float2*)&outF[(size_t)rm * DH + cn]       = make_float2(c0, c1);
                *(float2*)&outF[(size_t)(rm + 8) * DH + cn] = make_float2(c2, c3);
            }
            if (outHi) {
                __nv_bfloat16 h0 = __float2bfloat16(c0);
                __nv_bfloat16 h1 = __float2bfloat16(c1);
                __nv_bfloat16 h2 = __float2bfloat16(c2);
                __nv_bfloat16 h3 = __float2bfloat16(c3);
                __nv_bfloat162 hp0; hp0.x = h0; hp0.y = h1;
                __nv_bfloat162 hp1; hp1.x = h2; hp1.y = h3;
                __nv_bfloat162 lp0;
                lp0.x = __float2bfloat16(c0 - __bfloat162float(h0));
                lp0.y = __float2bfloat16(c1 - __bfloat162float(h1));
                __nv_bfloat162 lp1;
                lp1.x = __float2bfloat16(c2 - __bfloat162float(h2));
                lp1.y = __float2bfloat16(c3 - __bfloat162float(h3));
                *(__nv_bfloat162*)&outHi[(size_t)rm * DH + cn]       = hp0;
                *(__nv_bfloat162*)&outHi[(size_t)(rm + 8) * DH + cn] = hp1;
                *(__nv_bfloat162*)&outLo[(size_t)rm * DH + cn]       = lp0;
                *(__nv_bfloat162*)&outLo[(size_t)(rm + 8) * DH + cn] = lp1;
            }
        }
    }
}

// ---------------- fp32 -> bf16 hi/lo split -----------------------------------
__global__ __launch_bounds__(256) void split_kernel(
    const float* __restrict__ x, __nv_bfloat16* __restrict__ hi,
    __nv_bfloat16* __restrict__ lo, int n)
{
    int i = (blockIdx.x * 256 + threadIdx.x) * 4;
    if (i >= n) return;
    float4 v = *(const float4*)(x + i);
    __nv_bfloat16 h0 = __float2bfloat16(v.x), h1 = __float2bfloat16(v.y);
    __nv_bfloat16 h2 = __float2bfloat16(v.z), h3 = __float2bfloat16(v.w);
    __nv_bfloat162 hp0; hp0.x = h0; hp0.y = h1;
    __nv_bfloat162 hp1; hp1.x = h2; hp1.y = h3;
    __nv_bfloat162 lp0;
    lp0.x = __float2bfloat16(v.x - __bfloat162float(h0));
    lp0.y = __float2bfloat16(v.y - __bfloat162float(h1));
    __nv_bfloat162 lp1;
    lp1.x = __float2bfloat16(v.z - __bfloat162float(h2));
    lp1.y = __float2bfloat16(v.w - __bfloat162float(h3));
    *(__nv_bfloat162*)&hi[i]     = hp0;
    *(__nv_bfloat162*)&hi[i + 2] = hp1;
    *(__nv_bfloat162*)&lo[i]     = lp0;
    *(__nv_bfloat162*)&lo[i + 2] = lp1;
}

// ---------------- weight transpose + split: W[K,N] -> WT[N,K] hi/lo ----------
__global__ void trans_split_kernel(
    const float* __restrict__ W, __nv_bfloat16* __restrict__ hiT,
    __nv_bfloat16* __restrict__ loT)
{
    __shared__ float t[32][33];
    int n0 = blockIdx.x * 32, k0 = blockIdx.y * 32;
    int tx = threadIdx.x, ty = threadIdx.y;   // 32 x 8
    #pragma unroll
    for (int i = ty; i < 32; i += 8)
        t[i][tx] = W[(size_t)(k0 + i) * DH + n0 + tx];
    __syncthreads();
    #pragma unroll
    for (int i = ty; i < 32; i += 8) {
        float v = t[tx][i];                   // = W[k0+tx][n0+i]
        __nv_bfloat16 h = __float2bfloat16(v);
        __nv_bfloat16 l = __float2bfloat16(v - __bfloat162float(h));
        hiT[(size_t)(n0 + i) * DH + k0 + tx] = h;
        loT[(size_t)(n0 + i) * DH + k0 + tx] = l;
    }
}

// ================= SIMT parts (round-3 proven) ===============================
__device__ __forceinline__ unsigned long long pack_dup(float a) {
    unsigned long long r;
    asm("mov.b64 %0, {%1, %1};" : "=l"(r) : "f"(a));
    return r;
}
__device__ __forceinline__ void fma2(unsigned long long& d,
                                     unsigned long long a,
                                     unsigned long long b) {
    asm("fma.rn.f32x2 %0, %1, %2, %0;" : "+l"(d) : "l"(a), "l"(b));
}
__device__ __forceinline__ float2 unpack2(unsigned long long p) {
    float2 v;
    asm("mov.b64 {%0, %1}, %2;" : "=f"(v.x), "=f"(v.y) : "l"(p));
    return v;
}
__device__ __forceinline__ float block_reduce_sum_256(float val, float* red) {
    int tid = threadIdx.x;
    #pragma unroll
    for (int o = 16; o > 0; o >>= 1) val += __shfl_down_sync(0xffffffffu, val, o);
    if ((tid & 31) == 0) red[tid >> 5] = val;
    __syncthreads();
    if (tid < 8) {
        val = red[tid];
        #pragma unroll
        for (int o = 4; o > 0; o >>= 1) val += __shfl_down_sync(0xffu, val, o);
        if (tid == 0) red[0] = val;
    }
    __syncthreads();
    float r = red[0];
    __syncthreads();
    return r;
}

#define BM 128
#define BN 128
#define BK 8

#define MICRO_STEP2(ASBUF, BSBUF, kk)                                          \
    {                                                                          \
        float4 a0 = *(const float4*)&ASBUF[kk][ty * 8];                        \
        float4 a1 = *(const float4*)&ASBUF[kk][ty * 8 + 4];                    \
        ulonglong2 b0 = *(const ulonglong2*)&BSBUF[kk][tx * 8];                \
        ulonglong2 b1 = *(const ulonglong2*)&BSBUF[kk][tx * 8 + 4];            \
        unsigned long long rb2[4] = {b0.x, b0.y, b1.x, b1.y};                  \
        float ra[8] = {a0.x, a0.y, a0.z, a0.w, a1.x, a1.y, a1.z, a1.w};        \
        _Pragma("unroll")                                                      \
        for (int i = 0; i < 8; i++) {                                          \
            unsigned long long pa = pack_dup(ra[i]);                           \
            _Pragma("unroll")                                                  \
            for (int j = 0; j < 4; j++) fma2(acc2[i][j], pa, rb2[j]);          \
        }                                                                      \
    }

// Q-GEMM (NT, batched): Q = exp(20 * cos_sim)
__global__ __launch_bounds__(256) void qgemm_kernel(
    const float* __restrict__ tar, const float* __restrict__ ofc,
    const float* __restrict__ itn, const float* __restrict__ ifn,
    float* __restrict__ Q)
{
    const int K = DH;
    int b = blockIdx.z;
    const float* A  = tar + (size_t)b * LL * DH;
    const float* Bm = ofc + (size_t)b * LL * DH;

    __shared__ float As[2][BK][BM];
    __shared__ float Bs[2][BK][BN];
    int tid = threadIdx.x;
    int bm = blockIdx.y * BM;
    int bn = blockIdx.x * BN;
    int tx = tid & 15, ty = tid >> 4;

    unsigned long long acc2[8][4];
    #pragma unroll
    for (int i = 0; i < 8; i++)
        #pragma unroll
        for (int j = 0; j < 4; j++) acc2[i][j] = 0ull;

    int arow = tid >> 1, ak = (tid & 1) * 4;
    const float* Aptr = A  + (size_t)(bm + arow) * K + ak;
    const float* Bptr = Bm + (size_t)(bn + arow) * K + ak;

    float4 av = *(const float4*)(Aptr);
    float4 bv = *(const float4*)(Bptr);
    As[0][ak + 0][arow] = av.x; As[0][ak + 1][arow] = av.y;
    As[0][ak + 2][arow] = av.z; As[0][ak + 3][arow] = av.w;
    Bs[0][ak + 0][arow] = bv.x; Bs[0][ak + 1][arow] = bv.y;
    Bs[0][ak + 2][arow] = bv.z; Bs[0][ak + 3][arow] = bv.w;
    __syncthreads();

    int buf = 0;
    for (int k0 = BK; k0 < K + BK; k0 += BK) {
        if (k0 < K) {
            av = *(const float4*)(Aptr + k0);
            bv = *(const float4*)(Bptr + k0);
        }
        #pragma unroll
        for (int kk = 0; kk < BK; kk++) MICRO_STEP2(As[buf], Bs[buf], kk)
        if (k0 < K) {
            int nb = buf ^ 1;
            As[nb][ak + 0][arow] = av.x; As[nb][ak + 1][arow] = av.y;
            As[nb][ak + 2][arow] = av.z; As[nb][ak + 3][arow] = av.w;
            Bs[nb][ak + 0][arow] = bv.x; Bs[nb][ak + 1][arow] = bv.y;
            Bs[nb][ak + 2][arow] = bv.z; Bs[nb][ak + 3][arow] = bv.w;
            __syncthreads();
            buf = nb;
        }
    }

    float fo[8];
    #pragma unroll
    for (int j = 0; j < 8; j++) fo[j] = ifn[b * LL + bn + tx * 8 + j];
    #pragma unroll
    for (int i = 0; i < 8; i++) {
        int t = bm + ty * 8 + i;
        float sc_t = itn[b * LL + t] * 20.0f;
        float2 p0 = unpack2(acc2[i][0]);
        float2 p1 = unpack2(acc2[i][1]);
        float2 p2 = unpack2(acc2[i][2]);
        float2 p3 = unpack2(acc2[i][3]);
        float4 o0, o1;
        o0.x = expf(p0.x * sc_t * fo[0]);
        o0.y = expf(p0.y * sc_t * fo[1]);
        o0.z = expf(p1.x * sc_t * fo[2]);
        o0.w = expf(p1.y * sc_t * fo[3]);
        o1.x = expf(p2.x * sc_t * fo[4]);
        o1.y = expf(p2.y * sc_t * fo[5]);
        o1.z = expf(p3.x * sc_t * fo[6]);
        o1.w = expf(p3.y * sc_t * fo[7]);
        *(float4*)&Q[((size_t)b * LL + t) * LL + bn + tx * 8]     = o0;
        *(float4*)&Q[((size_t)b * LL + t) * LL + bn + tx * 8 + 4] = o1;
    }
}

// Final GEMM (NN, batched): out = rs_t*(Q @ (v*otp)) + tar
__global__ __launch_bounds__(256) void fgemm_kernel(
    const float* __restrict__ Q, const float* __restrict__ otp,
    const float* __restrict__ v, const float* __restrict__ rs,
    const float* __restrict__ tar, float* __restrict__ out)
{
    const int K = LL;
    const int N = DH;
    int b = blockIdx.z;
    const float* A  = Q   + (size_t)b * LL * LL;
    const float* Bm = otp + (size_t)b * LL * DH;

    __shared__ float As[2][BK][BM];
    __shared__ float Bs[2][BK][BN];
    int tid = threadIdx.x;
    int bm = blockIdx.y * BM;
    int bn = blockIdx.x * BN;
    int tx = tid & 15, ty = tid >> 4;

    unsigned long long acc2[8][4];
    #pragma unroll
    for (int i = 0; i < 8; i++)
        #pragma unroll
        for (int j = 0; j < 4; j++) acc2[i][j] = 0ull;

    int arow = tid >> 1, ak = (tid & 1) * 4;
    int bk  = tid >> 5, bn4 = (tid & 31) * 4;
    const float* Aptr = A  + (size_t)(bm + arow) * K + ak;
    const float* Bptr = Bm + (size_t)bk * N + bn + bn4;
    const float* vv   = v + b * LL;

    float4 av = *(const float4*)(Aptr);
    float4 bv = *(const float4*)(Bptr);
    float vs = vv[bk];
    As[0][ak + 0][arow] = av.x; As[0][ak + 1][arow] = av.y;
    As[0][ak + 2][arow] = av.z; As[0][ak + 3][arow] = av.w;
    bv.x *= vs; bv.y *= vs; bv.z *= vs; bv.w *= vs;
    *(float4*)&Bs[0][bk][bn4] = bv;
    __syncthreads();

    int buf = 0;
    for (int k0 = BK; k0 < K + BK; k0 += BK) {
        if (k0 < K) {
            av = *(const float4*)(Aptr + k0);
            bv = *(const float4*)(Bptr + (size_t)k0 * N);
            vs = vv[k0 + bk];
        }
        #pragma unroll
        for (int kk = 0; kk < BK; kk++) MICRO_STEP2(As[buf], Bs[buf], kk)
        if (k0 < K) {
            int nb = buf ^ 1;
            As[nb][ak + 0][arow] = av.x; As[nb][ak + 1][arow] = av.y;
            As[nb][ak + 2][arow] = av.z; As[nb][ak + 3][arow] = av.w;
            bv.x *= vs; bv.y *= vs; bv.z *= vs; bv.w *= vs;
            *(float4*)&Bs[nb][bk][bn4] = bv;
            __syncthreads();
            buf = nb;
        }
    }

    #pragma unroll
    for (int i = 0; i < 8; i++) {
        int t = bm + ty * 8 + i;
        int grow = b * LL + t;
        float r = rs[grow];
        const float* tp = &tar[(size_t)grow * DH + bn + tx * 8];
        float4 t0v = *(const float4*)tp;
        float4 t1v = *(const float4*)(tp + 4);
        float2 p0 = unpack2(acc2[i][0]);
        float2 p1 = unpack2(acc2[i][1]);
        float2 p2 = unpack2(acc2[i][2]);
        float2 p3 = unpack2(acc2[i][3]);
        float4 o0 = make_float4(r * p0.x + t0v.x, r * p0.y + t0v.y,
                                r * p1.x + t0v.z, r * p1.y + t0v.w);
        float4 o1 = make_float4(r * p2.x + t1v.x, r * p2.y + t1v.y,
                                r * p3.x + t1v.z, r * p3.y + t1v.w);
        *(float4*)&out[(size_t)grow * DH + bn + tx * 8]     = o0;
        *(float4*)&out[(size_t)grow * DH + bn + tx * 8 + 4] = o1;
    }
}

__global__ __launch_bounds__(256) void row_invnorm_kernel(
    const float* __restrict__ x, float* __restrict__ inv, float eps)
{
    __shared__ float red[8];
    int row = blockIdx.x;
    const float* p = x + (size_t)row * DH;
    float s = 0.f;
    for (int c = threadIdx.x; c < DH; c += 256) { float v = p[c]; s += v * v; }
    float tot = block_reduce_sum_256(s, red);
    if (threadIdx.x == 0) inv[row] = 1.0f / fmaxf(sqrtf(tot), eps);
}

__global__ void set_ones_kernel(float* p, int n) {
    int i = blockIdx.x * blockDim.x + threadIdx.x;
    if (i < n) p[i] = 1.0f;
}

__global__ void rowmv_kernel(const float* __restrict__ Q,
                             const float* __restrict__ v,
                             float* __restrict__ u)
{
    int t = blockIdx.x * 8 + threadIdx.y;
    int b = blockIdx.y;
    const float* row = Q + ((size_t)b * LL + t) * LL;
    const float* vv = v + b * LL;
    float s = 0.f;
    for (int o = threadIdx.x; o < LL; o += 32) s += row[o] * vv[o];
    #pragma unroll
    for (int off = 16; off > 0; off >>= 1) s += __shfl_down_sync(0xffffffffu, s, off);
    if (threadIdx.x == 0) u[b * LL + t] = 1.0f / s;
}

__global__ void colmv_kernel(const float* __restrict__ Q,
                             const float* __restrict__ u,
                             float* __restrict__ v)
{
    __shared__ float red[8][32];
    int o = blockIdx.x * 32 + threadIdx.x;
    int b = blockIdx.y;
    const float* uu = u + b * LL;
    float s = 0.f;
    for (int t = threadIdx.y; t < LL; t += 8)
        s += Q[((size_t)b * LL + t) * LL + o] * uu[t];
    red[threadIdx.y][threadIdx.x] = s;
    __syncthreads();
    if (threadIdx.y == 0) {
        float tot = 0.f;
        #pragma unroll
        for (int j = 0; j < 8; j++) tot += red[j][threadIdx.x];
        v[b * LL + o] = 1.0f / tot;
    }
}

__global__ void rowscale_kernel(const float* __restrict__ Q,
                                const float* __restrict__ v,
                                const float* __restrict__ u,
                                float* __restrict__ rs)
{
    int t = blockIdx.x * 8 + threadIdx.y;
    int b = blockIdx.y;
    const float* row = Q + ((size_t)b * LL + t) * LL;
    const float* vv = v + b * LL;
    float s = 0.f;
    for (int o = threadIdx.x; o < LL; o += 32) {
        float q = row[o] * vv[o];
        s += q * q;
    }
    #pragma unroll
    for (int off = 16; off > 0; off >>= 1) s += __shfl_down_sync(0xffffffffu, s, off);
    if (threadIdx.x == 0) {
        float ut = u[b * LL + t];
        rs[b * LL + t] = ut / fmaxf(ut * sqrtf(s), 1e-12f);
    }
}

__global__ __launch_bounds__(256) void ln_kernel(
    const float* __restrict__ x, const float* __restrict__ g,
    const float* __restrict__ beta, float* __restrict__ y)
{
    __shared__ float buf[DH];
    __shared__ float red[8];
    int row = blockIdx.x;
    const float* p = x + (size_t)row * DH;
    float s = 0.f;
    for (int c = threadIdx.x; c < DH; c += 256) { float v = p[c]; buf[c] = v; s += v; }
    float mean = block_reduce_sum_256(s, red) * (1.0f / DH);
    float s2 = 0.f;
    for (int c = threadIdx.x; c < DH; c += 256) { float d = buf[c] - mean; s2 += d * d; }
    float var = block_reduce_sum_256(s2, red) * (1.0f / DH);
    float inv = rsqrtf(var + 1e-5f);
    for (int c = threadIdx.x; c < DH; c += 256)
        y[(size_t)row * DH + c] = (buf[c] - mean) * inv * g[c] + beta[c];
}

// ---------------- launch -----------------------------------------------------
extern "C" void kernel_launch(void* const* d_in, const int* in_sizes, int n_in,
                              void* d_out, int out_size)
{
    const float* origin = (const float*)d_in[0];
    const float* target = (const float*)d_in[1];
    const float* W_ori = (const float*)d_in[2];  const float* b_ori = (const float*)d_in[3];
    const float* W_tar = (const float*)d_in[4];  const float* b_tar = (const float*)d_in[5];
    const float* W_ft  = (const float*)d_in[6];  const float* b_ft  = (const float*)d_in[7];
    const float* W_fo  = (const float*)d_in[8];  const float* b_fo  = (const float*)d_in[9];
    const float* W_fot = (const float*)d_in[10]; const float* b_fot = (const float*)d_in[11];
    const float* ln_g  = (const float*)d_in[12]; const float* ln_b  = (const float*)d_in[13];
    float* out = (float*)d_out;

    __nv_bfloat16 *ohi, *olo, *thi, *tlo, *orihi, *orilo, *t0hi, *t0lo, *wthi, *wtlo;
    float *tar, *ofc, *otp, *obuf, *Q, *itn, *ifn, *u, *v, *rs;
    cudaGetSymbolAddress((void**)&ohi,   g_ohi);
    cudaGetSymbolAddress((void**)&olo,   g_olo);
    cudaGetSymbolAddress((void**)&thi,   g_thi);
    cudaGetSymbolAddress((void**)&tlo,   g_tlo);
    cudaGetSymbolAddress((void**)&orihi, g_orihi);
    cudaGetSymbolAddress((void**)&orilo, g_orilo);
    cudaGetSymbolAddress((void**)&t0hi,  g_t0hi);
    cudaGetSymbolAddress((void**)&t0lo,  g_t0lo);
    cudaGetSymbolAddress((void**)&wthi,  g_wthi);
    cudaGetSymbolAddress((void**)&wtlo,  g_wtlo);
    cudaGetSymbolAddress((void**)&tar,   g_tar);
    cudaGetSymbolAddress((void**)&ofc,   g_ofc);
    cudaGetSymbolAddress((void**)&otp,   g_otp);
    cudaGetSymbolAddress((void**)&obuf,  g_obuf);
    cudaGetSymbolAddress((void**)&Q,     g_Q);
    cudaGetSymbolAddress((void**)&itn,   g_itn);
    cudaGetSymbolAddress((void**)&ifn,   g_ifn);
    cudaGetSymbolAddress((void**)&u,     g_u);
    cudaGetSymbolAddress((void**)&v,     g_v);
    cudaGetSymbolAddress((void**)&rs,    g_rs);

    const size_t WSZ = (size_t)DH * DH;
    const int NELEM = MTOT * DH;

    dim3 blk(256);

    // split activations to bf16 hi/lo
    split_kernel<<<NELEM / 4 / 256, blk>>>(origin, ohi, olo, NELEM);
    split_kernel<<<NELEM / 4 / 256, blk>>>(target, thi, tlo, NELEM);

    // transpose + split weights: W[K,N] -> WT[N,K] hi/lo
    dim3 tsg(32, 32), tsb(32, 8);
    trans_split_kernel<<<tsg, tsb>>>(W_ori, wthi + 0 * WSZ, wtlo + 0 * WSZ);
    trans_split_kernel<<<tsg, tsb>>>(W_tar, wthi + 1 * WSZ, wtlo + 1 * WSZ);
    trans_split_kernel<<<tsg, tsb>>>(W_ft,  wthi + 2 * WSZ, wtlo + 2 * WSZ);
    trans_split_kernel<<<tsg, tsb>>>(W_fo,  wthi + 3 * WSZ, wtlo + 3 * WSZ);
    trans_split_kernel<<<tsg, tsb>>>(W_fot, wthi + 4 * WSZ, wtlo + 4 * WSZ);

    // 5 dense GEMMs on tensor cores (bf16 3-term split via mma.sync)
    dim3 gtc(DH / 128, MTOT / 128);   // 8 x 64
    gemm_tc_kernel<<<gtc, blk>>>(ohi, olo, wthi + 0 * WSZ, wtlo + 0 * WSZ,
                                 b_ori, nullptr, orihi, orilo);
    gemm_tc_kernel<<<gtc, blk>>>(thi, tlo, wthi + 1 * WSZ, wtlo + 1 * WSZ,
                                 b_tar, nullptr, t0hi, t0lo);
    gemm_tc_kernel<<<gtc, blk>>>(t0hi, t0lo, wthi + 2 * WSZ, wtlo + 2 * WSZ,
                                 b_ft, tar, nullptr, nullptr);
    gemm_tc_kernel<<<gtc, blk>>>(orihi, orilo, wthi + 3 * WSZ, wtlo + 3 * WSZ,
                                 b_fo, ofc, nullptr, nullptr);
    gemm_tc_kernel<<<gtc, blk>>>(orihi, orilo, wthi + 4 * WSZ, wtlo + 4 * WSZ,
                                 b_fot, otp, nullptr, nullptr);

    // row inverse norms for cosine similarity
    row_invnorm_kernel<<<MTOT, blk>>>(tar, itn, 1e-8f);
    row_invnorm_kernel<<<MTOT, blk>>>(ofc, ifn, 1e-8f);

    // Q = exp(cos/0.05)
    qgemm_kernel<<<dim3(LL / BN, LL / BM, BB), blk>>>(tar, ofc, itn, ifn, Q);

    // Sinkhorn via scaling vectors: u = 1/(Qv), v = 1/(Q^T u), 5 iterations
    set_ones_kernel<<<(MTOT + 255) / 256, 256>>>(v, MTOT);
    for (int it = 0; it < 5; it++) {
        rowmv_kernel<<<dim3(LL / 8, BB), dim3(32, 8)>>>(Q, v, u);
        colmv_kernel<<<dim3(LL / 32, BB), dim3(32, 8)>>>(Q, u, v);
    }
    rowscale_kernel<<<dim3(LL / 8, BB), dim3(32, 8)>>>(Q, v, u, rs);

    // out = rs_t * (Q @ (v .* otp)) + tar
    fgemm_kernel<<<dim3(DH / BN, LL / BM, BB), blk>>>(Q, otp, v, rs, tar, obuf);

    // LayerNorm
    ln_kernel<<<MTOT, blk>>>(obuf, ln_g, ln_b, out);
}

// round 6
// speedup vs baseline: 2.7650x; 1.1009x over previous
#include <cuda_runtime.h>
#include <cuda_bf16.h>
#include <math.h>
#include <stdint.h>

// Problem dims (fixed by the dataset)
#define BB   16
#define LL   512
#define DIN  1024
#define DH   1024
#define MTOT (BB * LL)   // 8192

// ---------------- scratch (static __device__: allocation-free) --------------
__device__ __nv_bfloat16 g_ohi [(size_t)MTOT * DH];
__device__ __nv_bfloat16 g_olo [(size_t)MTOT * DH];
__device__ __nv_bfloat16 g_thi [(size_t)MTOT * DH];
__device__ __nv_bfloat16 g_tlo [(size_t)MTOT * DH];
__device__ __nv_bfloat16 g_orihi[(size_t)MTOT * DH];
__device__ __nv_bfloat16 g_orilo[(size_t)MTOT * DH];
__device__ __nv_bfloat16 g_t0hi[(size_t)MTOT * DH];
__device__ __nv_bfloat16 g_t0lo[(size_t)MTOT * DH];
__device__ __nv_bfloat16 g_tarhi[(size_t)MTOT * DH];
__device__ __nv_bfloat16 g_tarlo[(size_t)MTOT * DH];
__device__ __nv_bfloat16 g_ofchi[(size_t)MTOT * DH];
__device__ __nv_bfloat16 g_ofclo[(size_t)MTOT * DH];
__device__ __nv_bfloat16 g_Qhi [(size_t)BB * LL * LL];
__device__ __nv_bfloat16 g_Qlo [(size_t)BB * LL * LL];
__device__ __nv_bfloat16 g_vthi[(size_t)BB * DH * LL];
__device__ __nv_bfloat16 g_vtlo[(size_t)BB * DH * LL];
__device__ __nv_bfloat16 g_wthi[(size_t)5 * DH * DH];
__device__ __nv_bfloat16 g_wtlo[(size_t)5 * DH * DH];
__device__ float g_tar  [(size_t)MTOT * DH];
__device__ float g_ofc  [(size_t)MTOT * DH];
__device__ float g_otp  [(size_t)MTOT * DH];
__device__ float g_obuf [(size_t)MTOT * DH];
__device__ float g_Q    [(size_t)BB * LL * LL];
__device__ float g_itn  [MTOT];
__device__ float g_ifn  [MTOT];
__device__ float g_u    [MTOT];
__device__ float g_v    [MTOT];
__device__ float g_rs   [MTOT];

// ================= portable tensor-core helpers (sm_80 PTX) ==================
__device__ __forceinline__ uint32_t smem_u32(const void* p) {
    uint32_t a;
    asm("{ .reg .u64 t; cvta.to.shared.u64 t, %1; cvt.u32.u64 %0, t; }"
        : "=r"(a) : "l"(p));
    return a;
}
__device__ __forceinline__ void cp16(uint32_t s, const void* g) {
    asm volatile("cp.async.cg.shared.global [%0], [%1], 16;"
                 :: "r"(s), "l"(g) : "memory");
}
#define CP_COMMIT() asm volatile("cp.async.commit_group;" ::: "memory")
#define CP_WAIT(n)  asm volatile("cp.async.wait_group %0;" :: "n"(n) : "memory")

__device__ __forceinline__ void ldmx4(uint32_t* r, uint32_t addr) {
    asm volatile("ldmatrix.sync.aligned.m8n8.x4.shared.b16 {%0,%1,%2,%3}, [%4];"
        : "=r"(r[0]), "=r"(r[1]), "=r"(r[2]), "=r"(r[3]) : "r"(addr));
}
__device__ __forceinline__ void mma_bf16(float* d, const uint32_t* a,
                                         uint32_t b0, uint32_t b1) {
    asm volatile(
        "mma.sync.aligned.m16n8k16.row.col.f32.bf16.bf16.f32 "
        "{%0,%1,%2,%3}, {%4,%5,%6,%7}, {%8,%9}, {%0,%1,%2,%3};"
        : "+f"(d[0]), "+f"(d[1]), "+f"(d[2]), "+f"(d[3])
        : "r"(a[0]), "r"(a[1]), "r"(a[2]), "r"(a[3]), "r"(b0), "r"(b1));
}

// ===== shared mainloop: D(128x128 tile) = (Ahi+Alo)@(Bhi+Blo)^T, 3-term ======
// A*, B* are [rows, KDIM] K-major bf16. CTA 128x128, warp 64x32, K-chunk 32,
// cp.async double-buffered, ldmatrix fragments. acc layout per mma.sync.
typedef __nv_bfloat16 bf16;

template<int KDIM>
__device__ __forceinline__ void tc_core(
    const bf16* __restrict__ Ahi, const bf16* __restrict__ Alo,
    const bf16* __restrict__ Bhi, const bf16* __restrict__ Blo,
    int m0, int n0,
    bf16 (*As)[128][40], bf16 (*Bs)[128][40],
    float acc[4][4][4])
{
    const int CPS = KDIM / 32;        // chunks per segment
    const int NCHc = 3 * CPS;
    int tid = threadIdx.x;
    int lane = tid & 31, wid = tid >> 5;
    int warp_m = wid >> 2, warp_n = wid & 3;
    int prow = tid >> 1, pc0 = (tid & 1) * 2;

    uint32_t sA[2] = { smem_u32(&As[0][0][0]), smem_u32(&As[1][0][0]) };
    uint32_t sB[2] = { smem_u32(&Bs[0][0][0]), smem_u32(&Bs[1][0][0]) };

#define TC_PREFETCH(kc, b) {                                                   \
        int seg = (kc) / CPS;                                                  \
        int ko = ((kc) % CPS) * 32;                                            \
        const bf16* Asrc = (seg == 2) ? Alo : Ahi;                             \
        const bf16* Bsrc = (seg == 1) ? Blo : Bhi;                             \
        const bf16* ag = Asrc + (size_t)(m0 + prow) * KDIM + ko + pc0 * 8;     \
        const bf16* bg = Bsrc + (size_t)(n0 + prow) * KDIM + ko + pc0 * 8;     \
        uint32_t sa = sA[b] + prow * 80 + pc0 * 16;                            \
        uint32_t sb = sB[b] + prow * 80 + pc0 * 16;                            \
        cp16(sa, ag); cp16(sa + 16, ag + 8);                                   \
        cp16(sb, bg); cp16(sb + 16, bg + 8);                                   \
        CP_COMMIT(); }

    int mat = lane >> 3, mr = lane & 7;
    uint32_t aoff = (uint32_t)((warp_m * 64 + (mat & 1) * 8 + mr) * 80
                               + ((mat >> 1) * 8) * 2);
    uint32_t boff = (uint32_t)((warp_n * 32 + (mat >> 1) * 8 + mr) * 80
                               + ((mat & 1) * 8) * 2);

    #pragma unroll
    for (int mi = 0; mi < 4; mi++)
        #pragma unroll
        for (int ni = 0; ni < 4; ni++)
            #pragma unroll
            for (int e = 0; e < 4; e++) acc[mi][ni][e] = 0.f;

    TC_PREFETCH(0, 0)
    TC_PREFETCH(1, 1)

    for (int kc = 0; kc < NCHc; kc++) {
        if (kc == NCHc - 1) { CP_WAIT(0); } else { CP_WAIT(1); }
        __syncthreads();
        int b = kc & 1;
        #pragma unroll
        for (int ks = 0; ks < 32; ks += 16) {
            uint32_t afr[4][4];
            #pragma unroll
            for (int mi = 0; mi < 4; mi++)
                ldmx4(afr[mi], sA[b] + aoff + mi * (16 * 80) + ks * 2);
            uint32_t bfr[2][4];
            #pragma unroll
            for (int np = 0; np < 2; np++)
                ldmx4(bfr[np], sB[b] + boff + np * (16 * 80) + ks * 2);
            #pragma unroll
            for (int mi = 0; mi < 4; mi++)
                #pragma unroll
                for (int ni = 0; ni < 4; ni++)
                    mma_bf16(acc[mi][ni], afr[mi],
                             bfr[ni >> 1][(ni & 1) * 2],
                             bfr[ni >> 1][(ni & 1) * 2 + 1]);
        }
        __syncthreads();
        if (kc + 2 < NCHc) TC_PREFETCH(kc + 2, b)
    }
#undef TC_PREFETCH
}

// ---------------- dense GEMM + bias (+ optional fp32 / hi-lo outputs) --------
__global__ __launch_bounds__(256) void gemm_tc_kernel(
    const bf16* __restrict__ Ahi, const bf16* __restrict__ Alo,
    const bf16* __restrict__ Bhi, const bf16* __restrict__ Blo,
    const float* __restrict__ bias,
    float* __restrict__ outF,
    bf16* __restrict__ outHi, bf16* __restrict__ outLo)
{
    __shared__ __align__(16) bf16 As[2][128][40];
    __shared__ __align__(16) bf16 Bs[2][128][40];
    int m0 = blockIdx.y * 128, n0 = blockIdx.x * 128;
    float acc[4][4][4];
    tc_core<1024>(Ahi, Alo, Bhi, Blo, m0, n0, As, Bs, acc);

    int lane = threadIdx.x & 31, wid = threadIdx.x >> 5;
    int warp_m = wid >> 2, warp_n = wid & 3;
    int gid = lane >> 2, tig = lane & 3;
    #pragma unroll
    for (int ni = 0; ni < 4; ni++) {
        int cn = n0 + warp_n * 32 + ni * 8 + tig * 2;
        float bz0 = bias[cn], bz1 = bias[cn + 1];
        #pragma unroll
        for (int mi = 0; mi < 4; mi++) {
            int rm = m0 + warp_m * 64 + mi * 16 + gid;
            float c0 = acc[mi][ni][0] + bz0, c1 = acc[mi][ni][1] + bz1;
            float c2 = acc[mi][ni][2] + bz0, c3 = acc[mi][ni][3] + bz1;
            if (outF) {
                *(float2*)&outF[(size_t)rm * DH + cn]       = make_float2(c0, c1);
                *(float2*)&outF[(size_t)(rm + 8) * DH + cn] = make_float2(c2, c3);
            }
            if (outHi) {
                bf16 h0 = __float2bfloat16(c0), h1 = __float2bfloat16(c1);
                bf16 h2 = __float2bfloat16(c2), h3 = __float2bfloat16(c3);
                __nv_bfloat162 hp0; hp0.x = h0; hp0.y = h1;
                __nv_bfloat162 hp1; hp1.x = h2; hp1.y = h3;
                __nv_bfloat162 lp0;
                lp0.x = __float2bfloat16(c0 - __bfloat162float(h0));
                lp0.y = __float2bfloat16(c1 - __bfloat162float(h1));
                __nv_bfloat162 lp1;
                lp1.x = __float2bfloat16(c2 - __bfloat162float(h2));
                lp1.y = __float2bfloat16(c3 - __bfloat162float(h3));
                *(__nv_bfloat162*)&outHi[(size_t)rm * DH + cn]       = hp0;
                *(__nv_bfloat162*)&outHi[(size_t)(rm + 8) * DH + cn] = hp1;
                *(__nv_bfloat162*)&outLo[(size_t)rm * DH + cn]       = lp0;
                *(__nv_bfloat162*)&outLo[(size_t)(rm + 8) * DH + cn] = lp1;
            }
        }
    }
}

// ---------------- Q-GEMM (NT, batched): Q = exp(20*cos) + hi/lo split --------
__global__ __launch_bounds__(256) void qgemm_tc_kernel(
    const bf16* __restrict__ tarHi, const bf16* __restrict__ tarLo,
    const bf16* __restrict__ ofcHi, const bf16* __restrict__ ofcLo,
    const float* __restrict__ itn, const float* __restrict__ ifn,
    float* __restrict__ Q, bf16* __restrict__ Qhi, bf16* __restrict__ Qlo)
{
    __shared__ __align__(16) bf16 As[2][128][40];
    __shared__ __align__(16) bf16 Bs[2][128][40];
    int b = blockIdx.z;
    int m0 = blockIdx.y * 128, n0 = blockIdx.x * 128;
    const bf16* Ah = tarHi + (size_t)b * LL * DH;
    const bf16* Al = tarLo + (size_t)b * LL * DH;
    const bf16* Bh = ofcHi + (size_t)b * LL * DH;
    const bf16* Bl = ofcLo + (size_t)b * LL * DH;
    float acc[4][4][4];
    tc_core<1024>(Ah, Al, Bh, Bl, m0, n0, As, Bs, acc);

    int lane = threadIdx.x & 31, wid = threadIdx.x >> 5;
    int warp_m = wid >> 2, warp_n = wid & 3;
    int gid = lane >> 2, tig = lane & 3;
    #pragma unroll
    for (int ni = 0; ni < 4; ni++) {
        int cn = n0 + warp_n * 32 + ni * 8 + tig * 2;
        float f0 = ifn[b * LL + cn], f1 = ifn[b * LL + cn + 1];
        #pragma unroll
        for (int mi = 0; mi < 4; mi++) {
            int rm = m0 + warp_m * 64 + mi * 16 + gid;
            float s0 = itn[b * LL + rm] * 20.0f;
            float s1 = itn[b * LL + rm + 8] * 20.0f;
            float c0 = expf(acc[mi][ni][0] * s0 * f0);
            float c1 = expf(acc[mi][ni][1] * s0 * f1);
            float c2 = expf(acc[mi][ni][2] * s1 * f0);
            float c3 = expf(acc[mi][ni][3] * s1 * f1);
            size_t r0 = ((size_t)b * LL + rm) * LL + cn;
            size_t r1 = ((size_t)b * LL + rm + 8) * LL + cn;
            *(float2*)&Q[r0] = make_float2(c0, c1);
            *(float2*)&Q[r1] = make_float2(c2, c3);
            bf16 h0 = __float2bfloat16(c0), h1 = __float2bfloat16(c1);
            bf16 h2 = __float2bfloat16(c2), h3 = __float2bfloat16(c3);
            __nv_bfloat162 hp0; hp0.x = h0; hp0.y = h1;
            __nv_bfloat162 hp1; hp1.x = h2; hp1.y = h3;
            __nv_bfloat162 lp0;
            lp0.x = __float2bfloat16(c0 - __bfloat162float(h0));
            lp0.y = __float2bfloat16(c1 - __bfloat162float(h1));
            __nv_bfloat162 lp1;
            lp1.x = __float2bfloat16(c2 - __bfloat162float(h2));
            lp1.y = __float2bfloat16(c3 - __bfloat162float(h3));
            *(__nv_bfloat162*)&Qhi[r0] = hp0;
            *(__nv_bfloat162*)&Qhi[r1] = hp1;
            *(__nv_bfloat162*)&Qlo[r0] = lp0;
            *(__nv_bfloat162*)&Qlo[r1] = lp1;
        }
    }
}

// ---------------- Final GEMM (NT, batched): out = rs*(Q @ votp^T) + tar ------
__global__ __launch_bounds__(256) void fgemm_tc_kernel(
    const bf16* __restrict__ Qhi, const bf16* __restrict__ Qlo,
    const bf16* __restrict__ vtHi, const bf16* __restrict__ vtLo,
    const float* __restrict__ rs, const float* __restrict__ tar,
    float* __restrict__ out)
{
    __shared__ __align__(16) bf16 As[2][128][40];
    __shared__ __align__(16) bf16 Bs[2][128][40];
    int b = blockIdx.z;
    int m0 = blockIdx.y * 128, n0 = blockIdx.x * 128;
    const bf16* Ah = Qhi + (size_t)b * LL * LL;
    const bf16* Al = Qlo + (size_t)b * LL * LL;
    const bf16* Bh = vtHi + (size_t)b * DH * LL;
    const bf16* Bl = vtLo + (size_t)b * DH * LL;
    float acc[4][4][4];
    tc_core<512>(Ah, Al, Bh, Bl, m0, n0, As, Bs, acc);

    int lane = threadIdx.x & 31, wid = threadIdx.x >> 5;
    int warp_m = wid >> 2, warp_n = wid & 3;
    int gid = lane >> 2, tig = lane & 3;
    #pragma unroll
    for (int ni = 0; ni < 4; ni++) {
        int cn = n0 + warp_n * 32 + ni * 8 + tig * 2;
        #pragma unroll
        for (int mi = 0; mi < 4; mi++) {
            int rm = m0 + warp_m * 64 + mi * 16 + gid;
            int g0 = b * LL + rm, g1 = b * LL + rm + 8;
            float r0 = rs[g0], r1 = rs[g1];
            float2 t0 = *(const float2*)&tar[(size_t)g0 * DH + cn];
            float2 t1 = *(const float2*)&tar[(size_t)g1 * DH + cn];
            float2 o0 = make_float2(r0 * acc[mi][ni][0] + t0.x,
                                    r0 * acc[mi][ni][1] + t0.y);
            float2 o1 = make_float2(r1 * acc[mi][ni][2] + t1.x,
                                    r1 * acc[mi][ni][3] + t1.y);
            *(float2*)&out[(size_t)g0 * DH + cn] = o0;
            *(float2*)&out[(size_t)g1 * DH + cn] = o1;
        }
    }
}

// ---------------- fp32 -> bf16 hi/lo split -----------------------------------
__global__ __launch_bounds__(256) void split_kernel(
    const float* __restrict__ x, bf16* __restrict__ hi,
    bf16* __restrict__ lo, int n)
{
    int i = (blockIdx.x * 256 + threadIdx.x) * 4;
    if (i >= n) return;
    float4 v = *(const float4*)(x + i);
    bf16 h0 = __float2bfloat16(v.x), h1 = __float2bfloat16(v.y);
    bf16 h2 = __float2bfloat16(v.z), h3 = __float2bfloat16(v.w);
    __nv_bfloat162 hp0; hp0.x = h0; hp0.y = h1;
    __nv_bfloat162 hp1; hp1.x = h2; hp1.y = h3;
    __nv_bfloat162 lp0;
    lp0.x = __float2bfloat16(v.x - __bfloat162float(h0));
    lp0.y = __float2bfloat16(v.y - __bfloat162float(h1));
    __nv_bfloat162 lp1;
    lp1.x = __float2bfloat16(v.z - __bfloat162float(h2));
    lp1.y = __float2bfloat16(v.w - __bfloat162float(h3));
    *(__nv_bfloat162*)&hi[i]     = hp0;
    *(__nv_bfloat162*)&hi[i + 2] = hp1;
    *(__nv_bfloat162*)&lo[i]     = lp0;
    *(__nv_bfloat162*)&lo[i + 2] = lp1;
}

// ---------------- weight transpose + split: W[K,N] -> WT[N,K] hi/lo ----------
__global__ void trans_split_kernel(
    const float* __restrict__ W, bf16* __restrict__ hiT, bf16* __restrict__ loT)
{
    __shared__ float t[32][33];
    int n0 = blockIdx.x * 32, k0 = blockIdx.y * 32;
    int tx = threadIdx.x, ty = threadIdx.y;   // 32 x 8
    #pragma unroll
    for (int i = ty; i < 32; i += 8)
        t[i][tx] = W[(size_t)(k0 + i) * DH + n0 + tx];
    __syncthreads();
    #pragma unroll
    for (int i = ty; i < 32; i += 8) {
        float v = t[tx][i];
        bf16 h = __float2bfloat16(v);
        bf16 l = __float2bfloat16(v - __bfloat162float(h));
        hiT[(size_t)(n0 + i) * DH + k0 + tx] = h;
        loT[(size_t)(n0 + i) * DH + k0 + tx] = l;
    }
}

// ------- batched transpose+scale+split: vt[b][h][o] = otp[b][o][h]*v[b][o] ---
__global__ void vtrans_split_kernel(
    const float* __restrict__ otp, const float* __restrict__ v,
    bf16* __restrict__ hiT, bf16* __restrict__ loT)
{
    __shared__ float t[32][33];
    int b = blockIdx.z;
    int h0 = blockIdx.x * 32, o0 = blockIdx.y * 32;
    int tx = threadIdx.x, ty = threadIdx.y;   // 32 x 8
    const float* src = otp + (size_t)b * LL * DH;
    #pragma unroll
    for (int i = ty; i < 32; i += 8)
        t[i][tx] = src[(size_t)(o0 + i) * DH + h0 + tx] * v[b * LL + o0 + i];
    __syncthreads();
    bf16* hb = hiT + (size_t)b * DH * LL;
    bf16* lb = loT + (size_t)b * DH * LL;
    #pragma unroll
    for (int i = ty; i < 32; i += 8) {
        float x = t[tx][i];
        bf16 h = __float2bfloat16(x);
        bf16 l = __float2bfloat16(x - __bfloat162float(h));
        hb[(size_t)(h0 + i) * LL + o0 + tx] = h;
        lb[(size_t)(h0 + i) * LL + o0 + tx] = l;
    }
}

// ================= small SIMT kernels ========================================
__device__ __forceinline__ float block_reduce_sum_256(float val, float* red) {
    int tid = threadIdx.x;
    #pragma unroll
    for (int o = 16; o > 0; o >>= 1) val += __shfl_down_sync(0xffffffffu, val, o);
    if ((tid & 31) == 0) red[tid >> 5] = val;
    __syncthreads();
    if (tid < 8) {
        val = red[tid];
        #pragma unroll
        for (int o = 4; o > 0; o >>= 1) val += __shfl_down_sync(0xffu, val, o);
        if (tid == 0) red[0] = val;
    }
    __syncthreads();
    float r = red[0];
    __syncthreads();
    return r;
}

__global__ __launch_bounds__(256) void row_invnorm_kernel(
    const float* __restrict__ x, float* __restrict__ inv, float eps)
{
    __shared__ float red[8];
    int row = blockIdx.x;
    const float* p = x + (size_t)row * DH;
    float s = 0.f;
    for (int c = threadIdx.x; c < DH; c += 256) { float v = p[c]; s += v * v; }
    float tot = block_reduce_sum_256(s, red);
    if (threadIdx.x == 0) inv[row] = 1.0f / fmaxf(sqrtf(tot), eps);
}

__global__ void set_ones_kernel(float* p, int n) {
    int i = blockIdx.x * blockDim.x + threadIdx.x;
    if (i < n) p[i] = 1.0f;
}

__global__ void rowmv_kernel(const float* __restrict__ Q,
                             const float* __restrict__ v,
                             float* __restrict__ u)
{
    int t = blockIdx.x * 8 + threadIdx.y;
    int b = blockIdx.y;
    const float* row = Q + ((size_t)b * LL + t) * LL;
    const float* vv = v + b * LL;
    float s = 0.f;
    for (int o = threadIdx.x; o < LL; o += 32) s += row[o] * vv[o];
    #pragma unroll
    for (int off = 16; off > 0; off >>= 1) s += __shfl_down_sync(0xffffffffu, s, off);
    if (threadIdx.x == 0) u[b * LL + t] = 1.0f / s;
}

__global__ void colmv_kernel(const float* __restrict__ Q,
                             const float* __restrict__ u,
                             float* __restrict__ v)
{
    __shared__ float red[8][32];
    int o = blockIdx.x * 32 + threadIdx.x;
    int b = blockIdx.y;
    const float* uu = u + b * LL;
    float s = 0.f;
    for (int t = threadIdx.y; t < LL; t += 8)
        s += Q[((size_t)b * LL + t) * LL + o] * uu[t];
    red[threadIdx.y][threadIdx.x] = s;
    __syncthreads();
    if (threadIdx.y == 0) {
        float tot = 0.f;
        #pragma unroll
        for (int j = 0; j < 8; j++) tot += red[j][threadIdx.x];
        v[b * LL + o] = 1.0f / tot;
    }
}

__global__ void rowscale_kernel(const float* __restrict__ Q,
                                const float* __restrict__ v,
                                const float* __restrict__ u,
                                float* __restrict__ rs)
{
    int t = blockIdx.x * 8 + threadIdx.y;
    int b = blockIdx.y;
    const float* row = Q + ((size_t)b * LL + t) * LL;
    const float* vv = v + b * LL;
    float s = 0.f;
    for (int o = threadIdx.x; o < LL; o += 32) {
        float q = row[o] * vv[o];
        s += q * q;
    }
    #pragma unroll
    for (int off = 16; off > 0; off >>= 1) s += __shfl_down_sync(0xffffffffu, s, off);
    if (threadIdx.x == 0) {
        float ut = u[b * LL + t];
        rs[b * LL + t] = ut / fmaxf(ut * sqrtf(s), 1e-12f);
    }
}

__global__ __launch_bounds__(256) void ln_kernel(
    const float* __restrict__ x, const float* __restrict__ g,
    const float* __restrict__ beta, float* __restrict__ y)
{
    __shared__ float buf[DH];
    __shared__ float red[8];
    int row = blockIdx.x;
    const float* p = x + (size_t)row * DH;
    float s = 0.f;
    for (int c = threadIdx.x; c < DH; c += 256) { float v = p[c]; buf[c] = v; s += v; }
    float mean = block_reduce_sum_256(s, red) * (1.0f / DH);
    float s2 = 0.f;
    for (int c = threadIdx.x; c < DH; c += 256) { float d = buf[c] - mean; s2 += d * d; }
    float var = block_reduce_sum_256(s2, red) * (1.0f / DH);
    float inv = rsqrtf(var + 1e-5f);
    for (int c = threadIdx.x; c < DH; c += 256)
        y[(size_t)row * DH + c] = (buf[c] - mean) * inv * g[c] + beta[c];
}

// ---------------- launch -----------------------------------------------------
extern "C" void kernel_launch(void* const* d_in, const int* in_sizes, int n_in,
                              void* d_out, int out_size)
{
    const float* origin = (const float*)d_in[0];
    const float* target = (const float*)d_in[1];
    const float* W_ori = (const float*)d_in[2];  const float* b_ori = (const float*)d_in[3];
    const float* W_tar = (const float*)d_in[4];  const float* b_tar = (const float*)d_in[5];
    const float* W_ft  = (const float*)d_in[6];  const float* b_ft  = (const float*)d_in[7];
    const float* W_fo  = (const float*)d_in[8];  const float* b_fo  = (const float*)d_in[9];
    const float* W_fot = (const float*)d_in[10]; const float* b_fot = (const float*)d_in[11];
    const float* ln_g  = (const float*)d_in[12]; const float* ln_b  = (const float*)d_in[13];
    float* out = (float*)d_out;

    bf16 *ohi, *olo, *thi, *tlo, *orihi, *orilo, *t0hi, *t0lo;
    bf16 *tarhi, *tarlo, *ofchi, *ofclo, *Qhi, *Qlo, *vthi, *vtlo, *wthi, *wtlo;
    float *tar, *ofc, *otp, *obuf, *Q, *itn, *ifn, *u, *v, *rs;
    cudaGetSymbolAddress((void**)&ohi,   g_ohi);
    cudaGetSymbolAddress((void**)&olo,   g_olo);
    cudaGetSymbolAddress((void**)&thi,   g_thi);
    cudaGetSymbolAddress((void**)&tlo,   g_tlo);
    cudaGetSymbolAddress((void**)&orihi, g_orihi);
    cudaGetSymbolAddress((void**)&orilo, g_orilo);
    cudaGetSymbolAddress((void**)&t0hi,  g_t0hi);
    cudaGetSymbolAddress((void**)&t0lo,  g_t0lo);
    cudaGetSymbolAddress((void**)&tarhi, g_tarhi);
    cudaGetSymbolAddress((void**)&tarlo, g_tarlo);
    cudaGetSymbolAddress((void**)&ofchi, g_ofchi);
    cudaGetSymbolAddress((void**)&ofclo, g_ofclo);
    cudaGetSymbolAddress((void**)&Qhi,   g_Qhi);
    cudaGetSymbolAddress((void**)&Qlo,   g_Qlo);
    cudaGetSymbolAddress((void**)&vthi,  g_vthi);
    cudaGetSymbolAddress((void**)&vtlo,  g_vtlo);
    cudaGetSymbolAddress((void**)&wthi,  g_wthi);
    cudaGetSymbolAddress((void**)&wtlo,  g_wtlo);
    cudaGetSymbolAddress((void**)&tar,   g_tar);
    cudaGetSymbolAddress((void**)&ofc,   g_ofc);
    cudaGetSymbolAddress((void**)&otp,   g_otp);
    cudaGetSymbolAddress((void**)&obuf,  g_obuf);
    cudaGetSymbolAddress((void**)&Q,     g_Q);
    cudaGetSymbolAddress((void**)&itn,   g_itn);
    cudaGetSymbolAddress((void**)&ifn,   g_ifn);
    cudaGetSymbolAddress((void**)&u,     g_u);
    cudaGetSymbolAddress((void**)&v,     g_v);
    cudaGetSymbolAddress((void**)&rs,    g_rs);

    const size_t WSZ = (size_t)DH * DH;
    const int NELEM = MTOT * DH;

    dim3 blk(256);

    // split activations to bf16 hi/lo
    split_kernel<<<NELEM / 4 / 256, blk>>>(origin, ohi, olo, NELEM);
    split_kernel<<<NELEM / 4 / 256, blk>>>(target, thi, tlo, NELEM);

    // transpose + split weights: W[K,N] -> WT[N,K] hi/lo
    dim3 tsg(32, 32), tsb(32, 8);
    trans_split_kernel<<<tsg, tsb>>>(W_ori, wthi + 0 * WSZ, wtlo + 0 * WSZ);
    trans_split_kernel<<<tsg, tsb>>>(W_tar, wthi + 1 * WSZ, wtlo + 1 * WSZ);
    trans_split_kernel<<<tsg, tsb>>>(W_ft,  wthi + 2 * WSZ, wtlo + 2 * WSZ);
    trans_split_kernel<<<tsg, tsb>>>(W_fo,  wthi + 3 * WSZ, wtlo + 3 * WSZ);
    trans_split_kernel<<<tsg, tsb>>>(W_fot, wthi + 4 * WSZ, wtlo + 4 * WSZ);

    // 5 dense GEMMs on tensor cores (bf16 3-term split via mma.sync)
    dim3 gtc(DH / 128, MTOT / 128);   // 8 x 64
    gemm_tc_kernel<<<gtc, blk>>>(ohi, olo, wthi + 0 * WSZ, wtlo + 0 * WSZ,
                                 b_ori, nullptr, orihi, orilo);
    gemm_tc_kernel<<<gtc, blk>>>(thi, tlo, wthi + 1 * WSZ, wtlo + 1 * WSZ,
                                 b_tar, nullptr, t0hi, t0lo);
    gemm_tc_kernel<<<gtc, blk>>>(t0hi, t0lo, wthi + 2 * WSZ, wtlo + 2 * WSZ,
                                 b_ft, tar, tarhi, tarlo);
    gemm_tc_kernel<<<gtc, blk>>>(orihi, orilo, wthi + 3 * WSZ, wtlo + 3 * WSZ,
                                 b_fo, ofc, ofchi, ofclo);
    gemm_tc_kernel<<<gtc, blk>>>(orihi, orilo, wthi + 4 * WSZ, wtlo + 4 * WSZ,
                                 b_fot, otp, nullptr, nullptr);

    // row inverse norms for cosine similarity
    row_invnorm_kernel<<<MTOT, blk>>>(tar, itn, 1e-8f);
    row_invnorm_kernel<<<MTOT, blk>>>(ofc, ifn, 1e-8f);

    // Q = exp(cos/0.05) on tensor cores, with hi/lo split for the final GEMM
    qgemm_tc_kernel<<<dim3(LL / 128, LL / 128, BB), blk>>>(
        tarhi, tarlo, ofchi, ofclo, itn, ifn, Q, Qhi, Qlo);

    // Sinkhorn via scaling vectors: u = 1/(Qv), v = 1/(Q^T u), 5 iterations
    set_ones_kernel<<<(MTOT + 255) / 256, 256>>>(v, MTOT);
    for (int it = 0; it < 5; it++) {
        rowmv_kernel<<<dim3(LL / 8, BB), dim3(32, 8)>>>(Q, v, u);
        colmv_kernel<<<dim3(LL / 32, BB), dim3(32, 8)>>>(Q, u, v);
    }
    rowscale_kernel<<<dim3(LL / 8, BB), dim3(32, 8)>>>(Q, v, u, rs);

    // (v .* otp) transposed + split per batch: vt[b][h][o]
    vtrans_split_kernel<<<dim3(DH / 32, LL / 32, BB), tsb>>>(otp, v, vthi, vtlo);

    // out = rs_t * (Q @ vt^T) + tar on tensor cores
    fgemm_tc_kernel<<<dim3(DH / 128, LL / 128, BB), blk>>>(
        Qhi, Qlo, vthi, vtlo, rs, tar, obuf);

    // LayerNorm
    ln_kernel<<<MTOT, blk>>>(obuf, ln_g, ln_b, out);
}

// round 7
// speedup vs baseline: 2.8535x; 1.0320x over previous
#include <cuda_runtime.h>
#include <cuda_bf16.h>
#include <math.h>
#include <stdint.h>

// Problem dims (fixed by the dataset)
#define BB   16
#define LL   512
#define DIN  1024
#define DH   1024
#define MTOT (BB * LL)   // 8192

// ---------------- scratch (static __device__: allocation-free) --------------
__device__ __nv_bfloat16 g_ohi [(size_t)MTOT * DH];
__device__ __nv_bfloat16 g_olo [(size_t)MTOT * DH];
__device__ __nv_bfloat16 g_thi [(size_t)MTOT * DH];
__device__ __nv_bfloat16 g_tlo [(size_t)MTOT * DH];
__device__ __nv_bfloat16 g_orihi[(size_t)MTOT * DH];
__device__ __nv_bfloat16 g_orilo[(size_t)MTOT * DH];
__device__ __nv_bfloat16 g_t0hi[(size_t)MTOT * DH];
__device__ __nv_bfloat16 g_t0lo[(size_t)MTOT * DH];
__device__ __nv_bfloat16 g_tarhi[(size_t)MTOT * DH];
__device__ __nv_bfloat16 g_tarlo[(size_t)MTOT * DH];
__device__ __nv_bfloat16 g_ofchi[(size_t)MTOT * DH];
__device__ __nv_bfloat16 g_ofclo[(size_t)MTOT * DH];
__device__ __nv_bfloat16 g_Qhi [(size_t)BB * LL * LL];
__device__ __nv_bfloat16 g_Qlo [(size_t)BB * LL * LL];
__device__ __nv_bfloat16 g_vthi[(size_t)BB * DH * LL];
__device__ __nv_bfloat16 g_vtlo[(size_t)BB * DH * LL];
__device__ __nv_bfloat16 g_wthi[(size_t)5 * DH * DH];
__device__ __nv_bfloat16 g_wtlo[(size_t)5 * DH * DH];
__device__ float g_tar  [(size_t)MTOT * DH];
__device__ float g_ofc  [(size_t)MTOT * DH];
__device__ float g_otp  [(size_t)MTOT * DH];
__device__ float g_obuf [(size_t)MTOT * DH];
__device__ float g_Q    [(size_t)BB * LL * LL];
__device__ float g_itn  [MTOT];
__device__ float g_ifn  [MTOT];
__device__ float g_u    [MTOT];
__device__ float g_v    [MTOT];
__device__ float g_rs   [MTOT];

// ================= portable tensor-core helpers (sm_80 PTX) ==================
__device__ __forceinline__ uint32_t smem_u32(const void* p) {
    uint32_t a;
    asm("{ .reg .u64 t; cvta.to.shared.u64 t, %1; cvt.u32.u64 %0, t; }"
        : "=r"(a) : "l"(p));
    return a;
}
__device__ __forceinline__ void cp16(uint32_t s, const void* g) {
    asm volatile("cp.async.cg.shared.global [%0], [%1], 16;"
                 :: "r"(s), "l"(g) : "memory");
}
#define CP_COMMIT() asm volatile("cp.async.commit_group;" ::: "memory")
#define CP_WAIT(n)  asm volatile("cp.async.wait_group %0;" :: "n"(n) : "memory")

__device__ __forceinline__ void ldmx4(uint32_t* r, uint32_t addr) {
    asm volatile("ldmatrix.sync.aligned.m8n8.x4.shared.b16 {%0,%1,%2,%3}, [%4];"
        : "=r"(r[0]), "=r"(r[1]), "=r"(r[2]), "=r"(r[3]) : "r"(addr));
}
__device__ __forceinline__ void mma_bf16(float* d, const uint32_t* a,
                                         uint32_t b0, uint32_t b1) {
    asm volatile(
        "mma.sync.aligned.m16n8k16.row.col.f32.bf16.bf16.f32 "
        "{%0,%1,%2,%3}, {%4,%5,%6,%7}, {%8,%9}, {%0,%1,%2,%3};"
        : "+f"(d[0]), "+f"(d[1]), "+f"(d[2]), "+f"(d[3])
        : "r"(a[0]), "r"(a[1]), "r"(a[2]), "r"(a[3]), "r"(b0), "r"(b1));
}

// ===== shared mainloop: D(128x128 tile) = (Ahi+Alo)@(Bhi+Blo)^T, 3-term ======
// A*, B* are [rows, KDIM] K-major bf16. CTA 128x128, warp 64x32, K-chunk 32,
// 4-stage cp.async ring in dynamic smem, ONE __syncthreads per chunk.
typedef __nv_bfloat16 bf16;

#define TCSTG 4
#define STAGE_BYTES 10240            // 128 rows * 80 B
#define TC_SMEM (2 * TCSTG * STAGE_BYTES)   // 81920

template<int KDIM>
__device__ __forceinline__ void tc_core(
    const bf16* __restrict__ Ahi, const bf16* __restrict__ Alo,
    const bf16* __restrict__ Bhi, const bf16* __restrict__ Blo,
    int m0, int n0, char* dsm, float acc[4][4][4])
{
    const int CPS = KDIM / 32;        // chunks per segment
    const int NCHc = 3 * CPS;
    int tid = threadIdx.x;
    int lane = tid & 31, wid = tid >> 5;
    int warp_m = wid >> 2, warp_n = wid & 3;
    int prow = tid >> 1, pc0 = (tid & 1) * 2;

    uint32_t base = smem_u32(dsm);
    uint32_t sA[TCSTG], sB[TCSTG];
    #pragma unroll
    for (int s = 0; s < TCSTG; s++) {
        sA[s] = base + s * STAGE_BYTES;
        sB[s] = base + TCSTG * STAGE_BYTES + s * STAGE_BYTES;
    }

#define TC_PREFETCH(kc, st) {                                                  \
        int seg = (kc) / CPS;                                                  \
        int ko = ((kc) % CPS) * 32;                                            \
        const bf16* Asrc = (seg == 2) ? Alo : Ahi;                             \
        const bf16* Bsrc = (seg == 1) ? Blo : Bhi;                             \
        const bf16* ag = Asrc + (size_t)(m0 + prow) * KDIM + ko + pc0 * 8;     \
        const bf16* bg = Bsrc + (size_t)(n0 + prow) * KDIM + ko + pc0 * 8;     \
        uint32_t sa = sA[st] + prow * 80 + pc0 * 16;                           \
        uint32_t sb = sB[st] + prow * 80 + pc0 * 16;                           \
        cp16(sa, ag); cp16(sa + 16, ag + 8);                                   \
        cp16(sb, bg); cp16(sb + 16, bg + 8);                                   \
        CP_COMMIT(); }

    int mat = lane >> 3, mr = lane & 7;
    uint32_t aoff = (uint32_t)((warp_m * 64 + (mat & 1) * 8 + mr) * 80
                               + ((mat >> 1) * 8) * 2);
    uint32_t boff = (uint32_t)((warp_n * 32 + (mat >> 1) * 8 + mr) * 80
                               + ((mat & 1) * 8) * 2);

    #pragma unroll
    for (int mi = 0; mi < 4; mi++)
        #pragma unroll
        for (int ni = 0; ni < 4; ni++)
            #pragma unroll
            for (int e = 0; e < 4; e++) acc[mi][ni][e] = 0.f;

    // fill first S-1 stages
    TC_PREFETCH(0, 0)
    TC_PREFETCH(1, 1)
    TC_PREFETCH(2, 2)

    for (int kc = 0; kc < NCHc; kc++) {
        CP_WAIT(TCSTG - 2);        // stage kc complete (3 initial + 1/iter)
        __syncthreads();           // all warps past previous compute; visibility
        int pkc = kc + TCSTG - 1;
        if (pkc < NCHc) { TC_PREFETCH(pkc, pkc & (TCSTG - 1)) }
        else { CP_COMMIT(); }      // keep group count aligned
        int b = kc & (TCSTG - 1);
        #pragma unroll
        for (int ks = 0; ks < 32; ks += 16) {
            uint32_t afr[4][4];
            #pragma unroll
            for (int mi = 0; mi < 4; mi++)
                ldmx4(afr[mi], sA[b] + aoff + mi * (16 * 80) + ks * 2);
            uint32_t bfr[2][4];
            #pragma unroll
            for (int np = 0; np < 2; np++)
                ldmx4(bfr[np], sB[b] + boff + np * (16 * 80) + ks * 2);
            #pragma unroll
            for (int mi = 0; mi < 4; mi++)
                #pragma unroll
                for (int ni = 0; ni < 4; ni++)
                    mma_bf16(acc[mi][ni], afr[mi],
                             bfr[ni >> 1][(ni & 1) * 2],
                             bfr[ni >> 1][(ni & 1) * 2 + 1]);
        }
    }
#undef TC_PREFETCH
}

// ---------------- dense GEMM + bias (+ optional fp32 / hi-lo outputs) --------
__global__ __launch_bounds__(256) void gemm_tc_kernel(
    const bf16* __restrict__ Ahi, const bf16* __restrict__ Alo,
    const bf16* __restrict__ Bhi, const bf16* __restrict__ Blo,
    const float* __restrict__ bias,
    float* __restrict__ outF,
    bf16* __restrict__ outHi, bf16* __restrict__ outLo)
{
    extern __shared__ char dsm[];
    int m0 = blockIdx.y * 128, n0 = blockIdx.x * 128;
    float acc[4][4][4];
    tc_core<1024>(Ahi, Alo, Bhi, Blo, m0, n0, dsm, acc);

    int lane = threadIdx.x & 31, wid = threadIdx.x >> 5;
    int warp_m = wid >> 2, warp_n = wid & 3;
    int gid = lane >> 2, tig = lane & 3;
    #pragma unroll
    for (int ni = 0; ni < 4; ni++) {
        int cn = n0 + warp_n * 32 + ni * 8 + tig * 2;
        float bz0 = bias[cn], bz1 = bias[cn + 1];
        #pragma unroll
        for (int mi = 0; mi < 4; mi++) {
            int rm = m0 + warp_m * 64 + mi * 16 + gid;
            float c0 = acc[mi][ni][0] + bz0, c1 = acc[mi][ni][1] + bz1;
            float c2 = acc[mi][ni][2] + bz0, c3 = acc[mi][ni][3] + bz1;
            if (outF) {
                *(float2*)&outF[(size_t)rm * DH + cn]       = make_float2(c0, c1);
                *(float2*)&outF[(size_t)(rm + 8) * DH + cn] = make_float2(c2, c3);
            }
            if (outHi) {
                bf16 h0 = __float2bfloat16(c0), h1 = __float2bfloat16(c1);
                bf16 h2 = __float2bfloat16(c2), h3 = __float2bfloat16(c3);
                __nv_bfloat162 hp0; hp0.x = h0; hp0.y = h1;
                __nv_bfloat162 hp1; hp1.x = h2; hp1.y = h3;
                __nv_bfloat162 lp0;
                lp0.x = __float2bfloat16(c0 - __bfloat162float(h0));
                lp0.y = __float2bfloat16(c1 - __bfloat162float(h1));
                __nv_bfloat162 lp1;
                lp1.x = __float2bfloat16(c2 - __bfloat162float(h2));
                lp1.y = __float2bfloat16(c3 - __bfloat162float(h3));
                *(__nv_bfloat162*)&outHi[(size_t)rm * DH + cn]       = hp0;
                *(__nv_bfloat162*)&outHi[(size_t)(rm + 8) * DH + cn] = hp1;
                *(__nv_bfloat162*)&outLo[(size_t)rm * DH + cn]       = lp0;
                *(__nv_bfloat162*)&outLo[(size_t)(rm + 8) * DH + cn] = lp1;
            }
        }
    }
}

// ---------------- Q-GEMM (NT, batched): Q = exp(20*cos) + hi/lo split --------
__global__ __launch_bounds__(256) void qgemm_tc_kernel(
    const bf16* __restrict__ tarHi, const bf16* __restrict__ tarLo,
    const bf16* __restrict__ ofcHi, const bf16* __restrict__ ofcLo,
    const float* __restrict__ itn, const float* __restrict__ ifn,
    float* __restrict__ Q, bf16* __restrict__ Qhi, bf16* __restrict__ Qlo)
{
    extern __shared__ char dsm[];
    int b = blockIdx.z;
    int m0 = blockIdx.y * 128, n0 = blockIdx.x * 128;
    const bf16* Ah = tarHi + (size_t)b * LL * DH;
    const bf16* Al = tarLo + (size_t)b * LL * DH;
    const bf16* Bh = ofcHi + (size_t)b * LL * DH;
    const bf16* Bl = ofcLo + (size_t)b * LL * DH;
    float acc[4][4][4];
    tc_core<1024>(Ah, Al, Bh, Bl, m0, n0, dsm, acc);

    int lane = threadIdx.x & 31, wid = threadIdx.x >> 5;
    int warp_m = wid >> 2, warp_n = wid & 3;
    int gid = lane >> 2, tig = lane & 3;
    #pragma unroll
    for (int ni = 0; ni < 4; ni++) {
        int cn = n0 + warp_n * 32 + ni * 8 + tig * 2;
        float f0 = ifn[b * LL + cn], f1 = ifn[b * LL + cn + 1];
        #pragma unroll
        for (int mi = 0; mi < 4; mi++) {
            int rm = m0 + warp_m * 64 + mi * 16 + gid;
            float s0 = itn[b * LL + rm] * 20.0f;
            float s1 = itn[b * LL + rm + 8] * 20.0f;
            float c0 = expf(acc[mi][ni][0] * s0 * f0);
            float c1 = expf(acc[mi][ni][1] * s0 * f1);
            float c2 = expf(acc[mi][ni][2] * s1 * f0);
            float c3 = expf(acc[mi][ni][3] * s1 * f1);
            size_t r0 = ((size_t)b * LL + rm) * LL + cn;
            size_t r1 = ((size_t)b * LL + rm + 8) * LL + cn;
            *(float2*)&Q[r0] = make_float2(c0, c1);
            *(float2*)&Q[r1] = make_float2(c2, c3);
            bf16 h0 = __float2bfloat16(c0), h1 = __float2bfloat16(c1);
            bf16 h2 = __float2bfloat16(c2), h3 = __float2bfloat16(c3);
            __nv_bfloat162 hp0; hp0.x = h0; hp0.y = h1;
            __nv_bfloat162 hp1; hp1.x = h2; hp1.y = h3;
            __nv_bfloat162 lp0;
            lp0.x = __float2bfloat16(c0 - __bfloat162float(h0));
            lp0.y = __float2bfloat16(c1 - __bfloat162float(h1));
            __nv_bfloat162 lp1;
            lp1.x = __float2bfloat16(c2 - __bfloat162float(h2));
            lp1.y = __float2bfloat16(c3 - __bfloat162float(h3));
            *(__nv_bfloat162*)&Qhi[r0] = hp0;
            *(__nv_bfloat162*)&Qhi[r1] = hp1;
            *(__nv_bfloat162*)&Qlo[r0] = lp0;
            *(__nv_bfloat162*)&Qlo[r1] = lp1;
        }
    }
}

// ---------------- Final GEMM (NT, batched): out = rs*(Q @ votp^T) + tar ------
__global__ __launch_bounds__(256) void fgemm_tc_kernel(
    const bf16* __restrict__ Qhi, const bf16* __restrict__ Qlo,
    const bf16* __restrict__ vtHi, const bf16* __restrict__ vtLo,
    const float* __restrict__ rs, const float* __restrict__ tar,
    float* __restrict__ out)
{
    extern __shared__ char dsm[];
    int b = blockIdx.z;
    int m0 = blockIdx.y * 128, n0 = blockIdx.x * 128;
    const bf16* Ah = Qhi + (size_t)b * LL * LL;
    const bf16* Al = Qlo + (size_t)b * LL * LL;
    const bf16* Bh = vtHi + (size_t)b * DH * LL;
    const bf16* Bl = vtLo + (size_t)b * DH * LL;
    float acc[4][4][4];
    tc_core<512>(Ah, Al, Bh, Bl, m0, n0, dsm, acc);

    int lane = threadIdx.x & 31, wid = threadIdx.x >> 5;
    int warp_m = wid >> 2, warp_n = wid & 3;
    int gid = lane >> 2, tig = lane & 3;
    #pragma unroll
    for (int ni = 0; ni < 4; ni++) {
        int cn = n0 + warp_n * 32 + ni * 8 + tig * 2;
        #pragma unroll
        for (int mi = 0; mi < 4; mi++) {
            int rm = m0 + warp_m * 64 + mi * 16 + gid;
            int g0 = b * LL + rm, g1 = b * LL + rm + 8;
            float r0 = rs[g0], r1 = rs[g1];
            float2 t0 = *(const float2*)&tar[(size_t)g0 * DH + cn];
            float2 t1 = *(const float2*)&tar[(size_t)g1 * DH + cn];
            float2 o0 = make_float2(r0 * acc[mi][ni][0] + t0.x,
                                    r0 * acc[mi][ni][1] + t0.y);
            float2 o1 = make_float2(r1 * acc[mi][ni][2] + t1.x,
                                    r1 * acc[mi][ni][3] + t1.y);
            *(float2*)&out[(size_t)g0 * DH + cn] = o0;
            *(float2*)&out[(size_t)g1 * DH + cn] = o1;
        }
    }
}

// ---------------- fp32 -> bf16 hi/lo split -----------------------------------
__global__ __launch_bounds__(256) void split_kernel(
    const float* __restrict__ x, bf16* __restrict__ hi,
    bf16* __restrict__ lo, int n)
{
    int i = (blockIdx.x * 256 + threadIdx.x) * 4;
    if (i >= n) return;
    float4 v = *(const float4*)(x + i);
    bf16 h0 = __float2bfloat16(v.x), h1 = __float2bfloat16(v.y);
    bf16 h2 = __float2bfloat16(v.z), h3 = __float2bfloat16(v.w);
    __nv_bfloat162 hp0; hp0.x = h0; hp0.y = h1;
    __nv_bfloat162 hp1; hp1.x = h2; hp1.y = h3;
    __nv_bfloat162 lp0;
    lp0.x = __float2bfloat16(v.x - __bfloat162float(h0));
    lp0.y = __float2bfloat16(v.y - __bfloat162float(h1));
    __nv_bfloat162 lp1;
    lp1.x = __float2bfloat16(v.z - __bfloat162float(h2));
    lp1.y = __float2bfloat16(v.w - __bfloat162float(h3));
    *(__nv_bfloat162*)&hi[i]     = hp0;
    *(__nv_bfloat162*)&hi[i + 2] = hp1;
    *(__nv_bfloat162*)&lo[i]     = lp0;
    *(__nv_bfloat162*)&lo[i + 2] = lp1;
}

// ---------------- weight transpose + split: W[K,N] -> WT[N,K] hi/lo ----------
__global__ void trans_split_kernel(
    const float* __restrict__ W, bf16* __restrict__ hiT, bf16* __restrict__ loT)
{
    __shared__ float t[32][33];
    int n0 = blockIdx.x * 32, k0 = blockIdx.y * 32;
    int tx = threadIdx.x, ty = threadIdx.y;   // 32 x 8
    #pragma unroll
    for (int i = ty; i < 32; i += 8)
        t[i][tx] = W[(size_t)(k0 + i) * DH + n0 + tx];
    __syncthreads();
    #pragma unroll
    for (int i = ty; i < 32; i += 8) {
        float v = t[tx][i];
        bf16 h = __float2bfloat16(v);
        bf16 l = __float2bfloat16(v - __bfloat162float(h));
        hiT[(size_t)(n0 + i) * DH + k0 + tx] = h;
        loT[(size_t)(n0 + i) * DH + k0 + tx] = l;
    }
}

// ------- batched transpose+scale+split: vt[b][h][o] = otp[b][o][h]*v[b][o] ---
__global__ void vtrans_split_kernel(
    const float* __restrict__ otp, const float* __restrict__ v,
    bf16* __restrict__ hiT, bf16* __restrict__ loT)
{
    __shared__ float t[32][33];
    int b = blockIdx.z;
    int h0 = blockIdx.x * 32, o0 = blockIdx.y * 32;
    int tx = threadIdx.x, ty = threadIdx.y;   // 32 x 8
    const float* src = otp + (size_t)b * LL * DH;
    #pragma unroll
    for (int i = ty; i < 32; i += 8)
        t[i][tx] = src[(size_t)(o0 + i) * DH + h0 + tx] * v[b * LL + o0 + i];
    __syncthreads();
    bf16* hb = hiT + (size_t)b * DH * LL;
    bf16* lb = loT + (size_t)b * DH * LL;
    #pragma unroll
    for (int i = ty; i < 32; i += 8) {
        float x = t[tx][i];
        bf16 h = __float2bfloat16(x);
        bf16 l = __float2bfloat16(x - __bfloat162float(h));
        hb[(size_t)(h0 + i) * LL + o0 + tx] = h;
        lb[(size_t)(h0 + i) * LL + o0 + tx] = l;
    }
}

// ================= small SIMT kernels ========================================
__device__ __forceinline__ float block_reduce_sum_256(float val, float* red) {
    int tid = threadIdx.x;
    #pragma unroll
    for (int o = 16; o > 0; o >>= 1) val += __shfl_down_sync(0xffffffffu, val, o);
    if ((tid & 31) == 0) red[tid >> 5] = val;
    __syncthreads();
    if (tid < 8) {
        val = red[tid];
        #pragma unroll
        for (int o = 4; o > 0; o >>= 1) val += __shfl_down_sync(0xffu, val, o);
        if (tid == 0) red[0] = val;
    }
    __syncthreads();
    float r = red[0];
    __syncthreads();
    return r;
}

__global__ __launch_bounds__(256) void row_invnorm_kernel(
    const float* __restrict__ x, float* __restrict__ inv, float eps)
{
    __shared__ float red[8];
    int row = blockIdx.x;
    const float* p = x + (size_t)row * DH;
    float s = 0.f;
    for (int c = threadIdx.x; c < DH; c += 256) { float v = p[c]; s += v * v; }
    float tot = block_reduce_sum_256(s, red);
    if (threadIdx.x == 0) inv[row] = 1.0f / fmaxf(sqrtf(tot), eps);
}

__global__ void set_ones_kernel(float* p, int n) {
    int i = blockIdx.x * blockDim.x + threadIdx.x;
    if (i < n) p[i] = 1.0f;
}

__global__ void rowmv_kernel(const float* __restrict__ Q,
                             const float* __restrict__ v,
                             float* __restrict__ u)
{
    int t = blockIdx.x * 8 + threadIdx.y;
    int b = blockIdx.y;
    const float* row = Q + ((size_t)b * LL + t) * LL;
    const float* vv = v + b * LL;
    float s = 0.f;
    for (int o = threadIdx.x; o < LL; o += 32) s += row[o] * vv[o];
    #pragma unroll
    for (int off = 16; off > 0; off >>= 1) s += __shfl_down_sync(0xffffffffu, s, off);
    if (threadIdx.x == 0) u[b * LL + t] = 1.0f / s;
}

__global__ void colmv_kernel(const float* __restrict__ Q,
                             const float* __restrict__ u,
                             float* __restrict__ v)
{
    __shared__ float red[8][32];
    int o = blockIdx.x * 32 + threadIdx.x;
    int b = blockIdx.y;
    const float* uu = u + b * LL;
    float s = 0.f;
    for (int t = threadIdx.y; t < LL; t += 8)
        s += Q[((size_t)b * LL + t) * LL + o] * uu[t];
    red[threadIdx.y][threadIdx.x] = s;
    __syncthreads();
    if (threadIdx.y == 0) {
        float tot = 0.f;
        #pragma unroll
        for (int j = 0; j < 8; j++) tot += red[j][threadIdx.x];
        v[b * LL + o] = 1.0f / tot;
    }
}

__global__ void rowscale_kernel(const float* __restrict__ Q,
                                const float* __restrict__ v,
                                const float* __restrict__ u,
                                float* __restrict__ rs)
{
    int t = blockIdx.x * 8 + threadIdx.y;
    int b = blockIdx.y;
    const float* row = Q + ((size_t)b * LL + t) * LL;
    const float* vv = v + b * LL;
    float s = 0.f;
    for (int o = threadIdx.x; o < LL; o += 32) {
        float q = row[o] * vv[o];
        s += q * q;
    }
    #pragma unroll
    for (int off = 16; off > 0; off >>= 1) s += __shfl_down_sync(0xffffffffu, s, off);
    if (threadIdx.x == 0) {
        float ut = u[b * LL + t];
        rs[b * LL + t] = ut / fmaxf(ut * sqrtf(s), 1e-12f);
    }
}

__global__ __launch_bounds__(256) void ln_kernel(
    const float* __restrict__ x, const float* __restrict__ g,
    const float* __restrict__ beta, float* __restrict__ y)
{
    __shared__ float buf[DH];
    __shared__ float red[8];
    int row = blockIdx.x;
    const float* p = x + (size_t)row * DH;
    float s = 0.f;
    for (int c = threadIdx.x; c < DH; c += 256) { float v = p[c]; buf[c] = v; s += v; }
    float mean = block_reduce_sum_256(s, red) * (1.0f / DH);
    float s2 = 0.f;
    for (int c = threadIdx.x; c < DH; c += 256) { float d = buf[c] - mean; s2 += d * d; }
    float var = block_reduce_sum_256(s2, red) * (1.0f / DH);
    float inv = rsqrtf(var + 1e-5f);
    for (int c = threadIdx.x; c < DH; c += 256)
        y[(size_t)row * DH + c] = (buf[c] - mean) * inv * g[c] + beta[c];
}

// ---------------- launch -----------------------------------------------------
extern "C" void kernel_launch(void* const* d_in, const int* in_sizes, int n_in,
                              void* d_out, int out_size)
{
    const float* origin = (const float*)d_in[0];
    const float* target = (const float*)d_in[1];
    const float* W_ori = (const float*)d_in[2];  const float* b_ori = (const float*)d_in[3];
    const float* W_tar = (const float*)d_in[4];  const float* b_tar = (const float*)d_in[5];
    const float* W_ft  = (const float*)d_in[6];  const float* b_ft  = (const float*)d_in[7];
    const float* W_fo  = (const float*)d_in[8];  const float* b_fo  = (const float*)d_in[9];
    const float* W_fot = (const float*)d_in[10]; const float* b_fot = (const float*)d_in[11];
    const float* ln_g  = (const float*)d_in[12]; const float* ln_b  = (const float*)d_in[13];
    float* out = (float*)d_out;

    bf16 *ohi, *olo, *thi, *tlo, *orihi, *orilo, *t0hi, *t0lo;
    bf16 *tarhi, *tarlo, *ofchi, *ofclo, *Qhi, *Qlo, *vthi, *vtlo, *wthi, *wtlo;
    float *tar, *ofc, *otp, *obuf, *Q, *itn, *ifn, *u, *v, *rs;
    cudaGetSymbolAddress((void**)&ohi,   g_ohi);
    cudaGetSymbolAddress((void**)&olo,   g_olo);
    cudaGetSymbolAddress((void**)&thi,   g_thi);
    cudaGetSymbolAddress((void**)&tlo,   g_tlo);
    cudaGetSymbolAddress((void**)&orihi, g_orihi);
    cudaGetSymbolAddress((void**)&orilo, g_orilo);
    cudaGetSymbolAddress((void**)&t0hi,  g_t0hi);
    cudaGetSymbolAddress((void**)&t0lo,  g_t0lo);
    cudaGetSymbolAddress((void**)&tarhi, g_tarhi);
    cudaGetSymbolAddress((void**)&tarlo, g_tarlo);
    cudaGetSymbolAddress((void**)&ofchi, g_ofchi);
    cudaGetSymbolAddress((void**)&ofclo, g_ofclo);
    cudaGetSymbolAddress((void**)&Qhi,   g_Qhi);
    cudaGetSymbolAddress((void**)&Qlo,   g_Qlo);
    cudaGetSymbolAddress((void**)&vthi,  g_vthi);
    cudaGetSymbolAddress((void**)&vtlo,  g_vtlo);
    cudaGetSymbolAddress((void**)&wthi,  g_wthi);
    cudaGetSymbolAddress((void**)&wtlo,  g_wtlo);
    cudaGetSymbolAddress((void**)&tar,   g_tar);
    cudaGetSymbolAddress((void**)&ofc,   g_ofc);
    cudaGetSymbolAddress((void**)&otp,   g_otp);
    cudaGetSymbolAddress((void**)&obuf,  g_obuf);
    cudaGetSymbolAddress((void**)&Q,     g_Q);
    cudaGetSymbolAddress((void**)&itn,   g_itn);
    cudaGetSymbolAddress((void**)&ifn,   g_ifn);
    cudaGetSymbolAddress((void**)&u,     g_u);
    cudaGetSymbolAddress((void**)&v,     g_v);
    cudaGetSymbolAddress((void**)&rs,    g_rs);

    const size_t WSZ = (size_t)DH * DH;
    const int NELEM = MTOT * DH;

    cudaFuncSetAttribute(gemm_tc_kernel,
                         cudaFuncAttributeMaxDynamicSharedMemorySize, TC_SMEM);
    cudaFuncSetAttribute(qgemm_tc_kernel,
                         cudaFuncAttributeMaxDynamicSharedMemorySize, TC_SMEM);
    cudaFuncSetAttribute(fgemm_tc_kernel,
                         cudaFuncAttributeMaxDynamicSharedMemorySize, TC_SMEM);

    dim3 blk(256);

    // split activations to bf16 hi/lo
    split_kernel<<<NELEM / 4 / 256, blk>>>(origin, ohi, olo, NELEM);
    split_kernel<<<NELEM / 4 / 256, blk>>>(target, thi, tlo, NELEM);

    // transpose + split weights: W[K,N] -> WT[N,K] hi/lo
    dim3 tsg(32, 32), tsb(32, 8);
    trans_split_kernel<<<tsg, tsb>>>(W_ori, wthi + 0 * WSZ, wtlo + 0 * WSZ);
    trans_split_kernel<<<tsg, tsb>>>(W_tar, wthi + 1 * WSZ, wtlo + 1 * WSZ);
    trans_split_kernel<<<tsg, tsb>>>(W_ft,  wthi + 2 * WSZ, wtlo + 2 * WSZ);
    trans_split_kernel<<<tsg, tsb>>>(W_fo,  wthi + 3 * WSZ, wtlo + 3 * WSZ);
    trans_split_kernel<<<tsg, tsb>>>(W_fot, wthi + 4 * WSZ, wtlo + 4 * WSZ);

    // 5 dense GEMMs on tensor cores (bf16 3-term split via mma.sync)
    dim3 gtc(DH / 128, MTOT / 128);   // 8 x 64
    gemm_tc_kernel<<<gtc, blk, TC_SMEM>>>(ohi, olo, wthi + 0 * WSZ, wtlo + 0 * WSZ,
                                          b_ori, nullptr, orihi, orilo);
    gemm_tc_kernel<<<gtc, blk, TC_SMEM>>>(thi, tlo, wthi + 1 * WSZ, wtlo + 1 * WSZ,
                                          b_tar, nullptr, t0hi, t0lo);
    gemm_tc_kernel<<<gtc, blk, TC_SMEM>>>(t0hi, t0lo, wthi + 2 * WSZ, wtlo + 2 * WSZ,
                                          b_ft, tar, tarhi, tarlo);
    gemm_tc_kernel<<<gtc, blk, TC_SMEM>>>(orihi, orilo, wthi + 3 * WSZ, wtlo + 3 * WSZ,
                                          b_fo, ofc, ofchi, ofclo);
    gemm_tc_kernel<<<gtc, blk, TC_SMEM>>>(orihi, orilo, wthi + 4 * WSZ, wtlo + 4 * WSZ,
                                          b_fot, otp, nullptr, nullptr);

    // row inverse norms for cosine similarity
    row_invnorm_kernel<<<MTOT, blk>>>(tar, itn, 1e-8f);
    row_invnorm_kernel<<<MTOT, blk>>>(ofc, ifn, 1e-8f);

    // Q = exp(cos/0.05) on tensor cores, with hi/lo split for the final GEMM
    qgemm_tc_kernel<<<dim3(LL / 128, LL / 128, BB), blk, TC_SMEM>>>(
        tarhi, tarlo, ofchi, ofclo, itn, ifn, Q, Qhi, Qlo);

    // Sinkhorn via scaling vectors: u = 1/(Qv), v = 1/(Q^T u), 5 iterations
    set_ones_kernel<<<(MTOT + 255) / 256, 256>>>(v, MTOT);
    for (int it = 0; it < 5; it++) {
        rowmv_kernel<<<dim3(LL / 8, BB), dim3(32, 8)>>>(Q, v, u);
        colmv_kernel<<<dim3(LL / 32, BB), dim3(32, 8)>>>(Q, u, v);
    }
    rowscale_kernel<<<dim3(LL / 8, BB), dim3(32, 8)>>>(Q, v, u, rs);

    // (v .* otp) transposed + split per batch: vt[b][h][o]
    vtrans_split_kernel<<<dim3(DH / 32, LL / 32, BB), tsb>>>(otp, v, vthi, vtlo);

    // out = rs_t * (Q @ vt^T) + tar on tensor cores
    fgemm_tc_kernel<<<dim3(DH / 128, LL / 128, BB), blk, TC_SMEM>>>(
        Qhi, Qlo, vthi, vtlo, rs, tar, obuf);

    // LayerNorm
    ln_kernel<<<MTOT, blk>>>(obuf, ln_g, ln_b, out);
}

// round 8
// speedup vs baseline: 3.7166x; 1.3025x over previous
#include <cuda_runtime.h>
#include <cuda_bf16.h>
#include <math.h>
#include <stdint.h>

// Problem dims (fixed by the dataset)
#define BB   16
#define LL   512
#define DIN  1024
#define DH   1024
#define MTOT (BB * LL)   // 8192
#define WSZ  ((size_t)DH * DH)

typedef __nv_bfloat16 bf16;

// ---------------- scratch (static __device__: allocation-free) --------------
__device__ bf16 g_ohi [(size_t)MTOT * DH];
__device__ bf16 g_olo [(size_t)MTOT * DH];
__device__ bf16 g_thi [(size_t)MTOT * DH];
__device__ bf16 g_tlo [(size_t)MTOT * DH];
__device__ bf16 g_tarhi[(size_t)MTOT * DH];
__device__ bf16 g_tarlo[(size_t)MTOT * DH];
__device__ bf16 g_ofchi[(size_t)MTOT * DH];
__device__ bf16 g_ofclo[(size_t)MTOT * DH];
__device__ bf16 g_woris_hi[WSZ], g_woris_lo[WSZ];   // W_ori plain split
__device__ bf16 g_wtars_hi[WSZ], g_wtars_lo[WSZ];   // W_tar plain split
__device__ bf16 g_wftT_hi[WSZ],  g_wftT_lo[WSZ];    // W_ft^T split
__device__ bf16 g_wfoT_hi[WSZ],  g_wfoT_lo[WSZ];    // W_fo^T split
__device__ bf16 g_wfotT_hi[WSZ], g_wfotT_lo[WSZ];   // W_fot^T split
__device__ bf16 g_wc_hi[3 * WSZ], g_wc_lo[3 * WSZ]; // composite W^T splits
__device__ float g_bc[3][DH];                       // composite biases
__device__ bf16 g_Qhi [(size_t)BB * LL * LL];
__device__ bf16 g_Qlo [(size_t)BB * LL * LL];
__device__ bf16 g_vthi[(size_t)BB * DH * LL];
__device__ bf16 g_vtlo[(size_t)BB * DH * LL];
__device__ float g_tar  [(size_t)MTOT * DH];
__device__ float g_ofc  [(size_t)MTOT * DH];
__device__ float g_otp  [(size_t)MTOT * DH];
__device__ float g_obuf [(size_t)MTOT * DH];
__device__ float g_Q    [(size_t)BB * LL * LL];
__device__ float g_itn  [MTOT];
__device__ float g_ifn  [MTOT];
__device__ float g_u    [MTOT];
__device__ float g_v    [MTOT];
__device__ float g_rs   [MTOT];

// ================= portable tensor-core helpers (sm_80 PTX) ==================
__device__ __forceinline__ uint32_t smem_u32(const void* p) {
    uint32_t a;
    asm("{ .reg .u64 t; cvta.to.shared.u64 t, %1; cvt.u32.u64 %0, t; }"
        : "=r"(a) : "l"(p));
    return a;
}
__device__ __forceinline__ void cp16(uint32_t s, const void* g) {
    asm volatile("cp.async.cg.shared.global [%0], [%1], 16;"
                 :: "r"(s), "l"(g) : "memory");
}
#define CP_COMMIT() asm volatile("cp.async.commit_group;" ::: "memory")
#define CP_WAIT(n)  asm volatile("cp.async.wait_group %0;" :: "n"(n) : "memory")

__device__ __forceinline__ void ldmx4(uint32_t* r, uint32_t addr) {
    asm volatile("ldmatrix.sync.aligned.m8n8.x4.shared.b16 {%0,%1,%2,%3}, [%4];"
        : "=r"(r[0]), "=r"(r[1]), "=r"(r[2]), "=r"(r[3]) : "r"(addr));
}
__device__ __forceinline__ void mma_bf16(float* d, const uint32_t* a,
                                         uint32_t b0, uint32_t b1) {
    asm volatile(
        "mma.sync.aligned.m16n8k16.row.col.f32.bf16.bf16.f32 "
        "{%0,%1,%2,%3}, {%4,%5,%6,%7}, {%8,%9}, {%0,%1,%2,%3};"
        : "+f"(d[0]), "+f"(d[1]), "+f"(d[2]), "+f"(d[3])
        : "r"(a[0]), "r"(a[1]), "r"(a[2]), "r"(a[3]), "r"(b0), "r"(b1));
}

// ===== shared mainloop: D(128x128 tile) = (Ahi+Alo)@(Bhi+Blo)^T, 3-term ======
#define TCSTG 4
#define STAGE_BYTES 10240            // 128 rows * 80 B
#define TC_SMEM (2 * TCSTG * STAGE_BYTES)   // 81920

template<int KDIM>
__device__ __forceinline__ void tc_core(
    const bf16* __restrict__ Ahi, const bf16* __restrict__ Alo,
    const bf16* __restrict__ Bhi, const bf16* __restrict__ Blo,
    int m0, int n0, char* dsm, float acc[4][4][4])
{
    const int CPS = KDIM / 32;        // chunks per segment
    const int NCHc = 3 * CPS;
    int tid = threadIdx.x;
    int lane = tid & 31, wid = tid >> 5;
    int warp_m = wid >> 2, warp_n = wid & 3;
    int prow = tid >> 1, pc0 = (tid & 1) * 2;

    uint32_t base = smem_u32(dsm);
    uint32_t sA[TCSTG], sB[TCSTG];
    #pragma unroll
    for (int s = 0; s < TCSTG; s++) {
        sA[s] = base + s * STAGE_BYTES;
        sB[s] = base + TCSTG * STAGE_BYTES + s * STAGE_BYTES;
    }

#define TC_PREFETCH(kc, st) {                                                  \
        int seg = (kc) / CPS;                                                  \
        int ko = ((kc) % CPS) * 32;                                            \
        const bf16* Asrc = (seg == 2) ? Alo : Ahi;                             \
        const bf16* Bsrc = (seg == 1) ? Blo : Bhi;                             \
        const bf16* ag = Asrc + (size_t)(m0 + prow) * KDIM + ko + pc0 * 8;     \
        const bf16* bg = Bsrc + (size_t)(n0 + prow) * KDIM + ko + pc0 * 8;     \
        uint32_t sa = sA[st] + prow * 80 + pc0 * 16;                           \
        uint32_t sb = sB[st] + prow * 80 + pc0 * 16;                           \
        cp16(sa, ag); cp16(sa + 16, ag + 8);                                   \
        cp16(sb, bg); cp16(sb + 16, bg + 8);                                   \
        CP_COMMIT(); }

    int mat = lane >> 3, mr = lane & 7;
    uint32_t aoff = (uint32_t)((warp_m * 64 + (mat & 1) * 8 + mr) * 80
                               + ((mat >> 1) * 8) * 2);
    uint32_t boff = (uint32_t)((warp_n * 32 + (mat >> 1) * 8 + mr) * 80
                               + ((mat & 1) * 8) * 2);

    #pragma unroll
    for (int mi = 0; mi < 4; mi++)
        #pragma unroll
        for (int ni = 0; ni < 4; ni++)
            #pragma unroll
            for (int e = 0; e < 4; e++) acc[mi][ni][e] = 0.f;

    TC_PREFETCH(0, 0)
    TC_PREFETCH(1, 1)
    TC_PREFETCH(2, 2)

    for (int kc = 0; kc < NCHc; kc++) {
        CP_WAIT(TCSTG - 2);
        __syncthreads();
        int pkc = kc + TCSTG - 1;
        if (pkc < NCHc) { TC_PREFETCH(pkc, pkc & (TCSTG - 1)) }
        else { CP_COMMIT(); }
        int b = kc & (TCSTG - 1);
        #pragma unroll
        for (int ks = 0; ks < 32; ks += 16) {
            uint32_t afr[4][4];
            #pragma unroll
            for (int mi = 0; mi < 4; mi++)
                ldmx4(afr[mi], sA[b] + aoff + mi * (16 * 80) + ks * 2);
            uint32_t bfr[2][4];
            #pragma unroll
            for (int np = 0; np < 2; np++)
                ldmx4(bfr[np], sB[b] + boff + np * (16 * 80) + ks * 2);
            #pragma unroll
            for (int mi = 0; mi < 4; mi++)
                #pragma unroll
                for (int ni = 0; ni < 4; ni++)
                    mma_bf16(acc[mi][ni], afr[mi],
                             bfr[ni >> 1][(ni & 1) * 2],
                             bfr[ni >> 1][(ni & 1) * 2 + 1]);
        }
    }
#undef TC_PREFETCH
}

// --------- epilogue helper: write fp32 / bf16 hi-lo from acc -----------------
__device__ __forceinline__ void tc_epilogue(
    float acc[4][4][4], int m0, int n0, const float* bias,
    float* outF, bf16* outHi, bf16* outLo)
{
    int lane = threadIdx.x & 31, wid = threadIdx.x >> 5;
    int warp_m = wid >> 2, warp_n = wid & 3;
    int gid = lane >> 2, tig = lane & 3;
    #pragma unroll
    for (int ni = 0; ni < 4; ni++) {
        int cn = n0 + warp_n * 32 + ni * 8 + tig * 2;
        float bz0 = bias ? bias[cn] : 0.f;
        float bz1 = bias ? bias[cn + 1] : 0.f;
        #pragma unroll
        for (int mi = 0; mi < 4; mi++) {
            int rm = m0 + warp_m * 64 + mi * 16 + gid;
            float c0 = acc[mi][ni][0] + bz0, c1 = acc[mi][ni][1] + bz1;
            float c2 = acc[mi][ni][2] + bz0, c3 = acc[mi][ni][3] + bz1;
            if (outF) {
                *(float2*)&outF[(size_t)rm * DH + cn]       = make_float2(c0, c1);
                *(float2*)&outF[(size_t)(rm + 8) * DH + cn] = make_float2(c2, c3);
            }
            if (outHi) {
                bf16 h0 = __float2bfloat16(c0), h1 = __float2bfloat16(c1);
                bf16 h2 = __float2bfloat16(c2), h3 = __float2bfloat16(c3);
                __nv_bfloat162 hp0; hp0.x = h0; hp0.y = h1;
                __nv_bfloat162 hp1; hp1.x = h2; hp1.y = h3;
                __nv_bfloat162 lp0;
                lp0.x = __float2bfloat16(c0 - __bfloat162float(h0));
                lp0.y = __float2bfloat16(c1 - __bfloat162float(h1));
                __nv_bfloat162 lp1;
                lp1.x = __float2bfloat16(c2 - __bfloat162float(h2));
                lp1.y = __float2bfloat16(c3 - __bfloat162float(h3));
                *(__nv_bfloat162*)&outHi[(size_t)rm * DH + cn]       = hp0;
                *(__nv_bfloat162*)&outHi[(size_t)(rm + 8) * DH + cn] = hp1;
                *(__nv_bfloat162*)&outLo[(size_t)rm * DH + cn]       = lp0;
                *(__nv_bfloat162*)&outLo[(size_t)(rm + 8) * DH + cn] = lp1;
            }
        }
    }
}

// --------- composite-weight GEMMs: WcT[z] = (Wz2^T) @ (Wz1)^T ---------------
// z=0: A=W_ft^T,  B=W_tar  -> WcT_tar
// z=1: A=W_fo^T,  B=W_ori  -> WcT_fo
// z=2: A=W_fot^T, B=W_ori  -> WcT_fot
__global__ __launch_bounds__(256) void wgemm3_kernel()
{
    extern __shared__ char dsm[];
    int z = blockIdx.z;
    int m0 = blockIdx.y * 128, n0 = blockIdx.x * 128;
    const bf16 *Ah, *Al, *Bh, *Bl;
    if (z == 0)      { Ah = g_wftT_hi;  Al = g_wftT_lo;  Bh = g_wtars_hi; Bl = g_wtars_lo; }
    else if (z == 1) { Ah = g_wfoT_hi;  Al = g_wfoT_lo;  Bh = g_woris_hi; Bl = g_woris_lo; }
    else             { Ah = g_wfotT_hi; Al = g_wfotT_lo; Bh = g_woris_hi; Bl = g_woris_lo; }
    float acc[4][4][4];
    tc_core<1024>(Ah, Al, Bh, Bl, m0, n0, dsm, acc);
    tc_epilogue(acc, m0, n0, nullptr, nullptr,
                g_wc_hi + (size_t)z * WSZ, g_wc_lo + (size_t)z * WSZ);
}

// --------- fused 3 big GEMMs -------------------------------------------------
// z=0: tar = target @ WcT_tar^T + bc0  (fp32 + hi/lo)
// z=1: ofc = origin @ WcT_fo^T + bc1   (fp32 + hi/lo)
// z=2: otp = origin @ WcT_fot^T + bc2  (fp32)
__global__ __launch_bounds__(256) void gemm3_tc_kernel()
{
    extern __shared__ char dsm[];
    int z = blockIdx.z;
    int m0 = blockIdx.y * 128, n0 = blockIdx.x * 128;
    const bf16 *Ah, *Al;
    float* outF;
    bf16 *oH, *oL;
    if (z == 0)      { Ah = g_thi; Al = g_tlo; outF = g_tar; oH = g_tarhi; oL = g_tarlo; }
    else if (z == 1) { Ah = g_ohi; Al = g_olo; outF = g_ofc; oH = g_ofchi; oL = g_ofclo; }
    else             { Ah = g_ohi; Al = g_olo; outF = g_otp; oH = nullptr; oL = nullptr; }
    const bf16* Bh = g_wc_hi + (size_t)z * WSZ;
    const bf16* Bl = g_wc_lo + (size_t)z * WSZ;
    float acc[4][4][4];
    tc_core<1024>(Ah, Al, Bh, Bl, m0, n0, dsm, acc);
    tc_epilogue(acc, m0, n0, g_bc[z], outF, oH, oL);
}

// ---------------- Q-GEMM (NT, batched): Q = exp(20*cos) + hi/lo split --------
__global__ __launch_bounds__(256) void qgemm_tc_kernel()
{
    extern __shared__ char dsm[];
    int b = blockIdx.z;
    int m0 = blockIdx.y * 128, n0 = blockIdx.x * 128;
    const bf16* Ah = g_tarhi + (size_t)b * LL * DH;
    const bf16* Al = g_tarlo + (size_t)b * LL * DH;
    const bf16* Bh = g_ofchi + (size_t)b * LL * DH;
    const bf16* Bl = g_ofclo + (size_t)b * LL * DH;
    float acc[4][4][4];
    tc_core<1024>(Ah, Al, Bh, Bl, m0, n0, dsm, acc);

    int lane = threadIdx.x & 31, wid = threadIdx.x >> 5;
    int warp_m = wid >> 2, warp_n = wid & 3;
    int gid = lane >> 2, tig = lane & 3;
    #pragma unroll
    for (int ni = 0; ni < 4; ni++) {
        int cn = n0 + warp_n * 32 + ni * 8 + tig * 2;
        float f0 = g_ifn[b * LL + cn], f1 = g_ifn[b * LL + cn + 1];
        #pragma unroll
        for (int mi = 0; mi < 4; mi++) {
            int rm = m0 + warp_m * 64 + mi * 16 + gid;
            float s0 = g_itn[b * LL + rm] * 20.0f;
            float s1 = g_itn[b * LL + rm + 8] * 20.0f;
            float c0 = expf(acc[mi][ni][0] * s0 * f0);
            float c1 = expf(acc[mi][ni][1] * s0 * f1);
            float c2 = expf(acc[mi][ni][2] * s1 * f0);
            float c3 = expf(acc[mi][ni][3] * s1 * f1);
            size_t r0 = ((size_t)b * LL + rm) * LL + cn;
            size_t r1 = ((size_t)b * LL + rm + 8) * LL + cn;
            *(float2*)&g_Q[r0] = make_float2(c0, c1);
            *(float2*)&g_Q[r1] = make_float2(c2, c3);
            bf16 h0 = __float2bfloat16(c0), h1 = __float2bfloat16(c1);
            bf16 h2 = __float2bfloat16(c2), h3 = __float2bfloat16(c3);
            __nv_bfloat162 hp0; hp0.x = h0; hp0.y = h1;
            __nv_bfloat162 hp1; hp1.x = h2; hp1.y = h3;
            __nv_bfloat162 lp0;
            lp0.x = __float2bfloat16(c0 - __bfloat162float(h0));
            lp0.y = __float2bfloat16(c1 - __bfloat162float(h1));
            __nv_bfloat162 lp1;
            lp1.x = __float2bfloat16(c2 - __bfloat162float(h2));
            lp1.y = __float2bfloat16(c3 - __bfloat162float(h3));
            *(__nv_bfloat162*)&g_Qhi[r0] = hp0;
            *(__nv_bfloat162*)&g_Qhi[r1] = hp1;
            *(__nv_bfloat162*)&g_Qlo[r0] = lp0;
            *(__nv_bfloat162*)&g_Qlo[r1] = lp1;
        }
    }
}

// ---------------- Final GEMM (NT, batched): out = rs*(Q @ votp^T) + tar ------
__global__ __launch_bounds__(256) void fgemm_tc_kernel()
{
    extern __shared__ char dsm[];
    int b = blockIdx.z;
    int m0 = blockIdx.y * 128, n0 = blockIdx.x * 128;
    const bf16* Ah = g_Qhi + (size_t)b * LL * LL;
    const bf16* Al = g_Qlo + (size_t)b * LL * LL;
    const bf16* Bh = g_vthi + (size_t)b * DH * LL;
    const bf16* Bl = g_vtlo + (size_t)b * DH * LL;
    float acc[4][4][4];
    tc_core<512>(Ah, Al, Bh, Bl, m0, n0, dsm, acc);

    int lane = threadIdx.x & 31, wid = threadIdx.x >> 5;
    int warp_m = wid >> 2, warp_n = wid & 3;
    int gid = lane >> 2, tig = lane & 3;
    #pragma unroll
    for (int ni = 0; ni < 4; ni++) {
        int cn = n0 + warp_n * 32 + ni * 8 + tig * 2;
        #pragma unroll
        for (int mi = 0; mi < 4; mi++) {
            int rm = m0 + warp_m * 64 + mi * 16 + gid;
            int g0 = b * LL + rm, g1 = b * LL + rm + 8;
            float r0 = g_rs[g0], r1 = g_rs[g1];
            float2 t0 = *(const float2*)&g_tar[(size_t)g0 * DH + cn];
            float2 t1 = *(const float2*)&g_tar[(size_t)g1 * DH + cn];
            float2 o0 = make_float2(r0 * acc[mi][ni][0] + t0.x,
                                    r0 * acc[mi][ni][1] + t0.y);
            float2 o1 = make_float2(r1 * acc[mi][ni][2] + t1.x,
                                    r1 * acc[mi][ni][3] + t1.y);
            *(float2*)&g_obuf[(size_t)g0 * DH + cn] = o0;
            *(float2*)&g_obuf[(size_t)g1 * DH + cn] = o1;
        }
    }
}

// ---------------- fp32 -> bf16 hi/lo split -----------------------------------
__global__ __launch_bounds__(256) void split_kernel(
    const float* __restrict__ x, bf16* __restrict__ hi,
    bf16* __restrict__ lo, int n)
{
    int i = (blockIdx.x * 256 + threadIdx.x) * 4;
    if (i >= n) return;
    float4 v = *(const float4*)(x + i);
    bf16 h0 = __float2bfloat16(v.x), h1 = __float2bfloat16(v.y);
    bf16 h2 = __float2bfloat16(v.z), h3 = __float2bfloat16(v.w);
    __nv_bfloat162 hp0; hp0.x = h0; hp0.y = h1;
    __nv_bfloat162 hp1; hp1.x = h2; hp1.y = h3;
    __nv_bfloat162 lp0;
    lp0.x = __float2bfloat16(v.x - __bfloat162float(h0));
    lp0.y = __float2bfloat16(v.y - __bfloat162float(h1));
    __nv_bfloat162 lp1;
    lp1.x = __float2bfloat16(v.z - __bfloat162float(h2));
    lp1.y = __float2bfloat16(v.w - __bfloat162float(h3));
    *(__nv_bfloat162*)&hi[i]     = hp0;
    *(__nv_bfloat162*)&hi[i + 2] = hp1;
    *(__nv_bfloat162*)&lo[i]     = lp0;
    *(__nv_bfloat162*)&lo[i + 2] = lp1;
}

// ---------------- weight transpose + split: W[K,N] -> WT[N,K] hi/lo ----------
__global__ void trans_split_kernel(
    const float* __restrict__ W, bf16* __restrict__ hiT, bf16* __restrict__ loT)
{
    __shared__ float t[32][33];
    int n0 = blockIdx.x * 32, k0 = blockIdx.y * 32;
    int tx = threadIdx.x, ty = threadIdx.y;   // 32 x 8
    #pragma unroll
    for (int i = ty; i < 32; i += 8)
        t[i][tx] = W[(size_t)(k0 + i) * DH + n0 + tx];
    __syncthreads();
    #pragma unroll
    for (int i = ty; i < 32; i += 8) {
        float v = t[tx][i];
        bf16 h = __float2bfloat16(v);
        bf16 l = __float2bfloat16(v - __bfloat162float(h));
        hiT[(size_t)(n0 + i) * DH + k0 + tx] = h;
        loT[(size_t)(n0 + i) * DH + k0 + tx] = l;
    }
}

// ---------------- composite biases: bc[z] -----------------------------------
// z=0: b_tar @ W_ft + b_ft ; z=1: b_ori @ W_fo + b_fo ; z=2: b_ori @ W_fot + b_fot
__global__ void bias_comb_kernel(
    const float* __restrict__ b_tar, const float* __restrict__ b_ori,
    const float* __restrict__ W_ft, const float* __restrict__ W_fo,
    const float* __restrict__ W_fot,
    const float* __restrict__ b_ft, const float* __restrict__ b_fo,
    const float* __restrict__ b_fot)
{
    int z = blockIdx.y;
    int n = blockIdx.x * 256 + threadIdx.x;
    const float* b1 = (z == 0) ? b_tar : b_ori;
    const float* W2 = (z == 0) ? W_ft : (z == 1) ? W_fo : W_fot;
    const float* b2 = (z == 0) ? b_ft : (z == 1) ? b_fo : b_fot;
    float s = 0.f;
    for (int k = 0; k < DH; k++) s += b1[k] * W2[(size_t)k * DH + n];
    g_bc[z][n] = s + b2[n];
}

// ------- batched transpose+scale+split: vt[b][h][o] = otp[b][o][h]*v[b][o] ---
__global__ void vtrans_split_kernel()
{
    __shared__ float t[32][33];
    int b = blockIdx.z;
    int h0 = blockIdx.x * 32, o0 = blockIdx.y * 32;
    int tx = threadIdx.x, ty = threadIdx.y;   // 32 x 8
    const float* src = g_otp + (size_t)b * LL * DH;
    #pragma unroll
    for (int i = ty; i < 32; i += 8)
        t[i][tx] = src[(size_t)(o0 + i) * DH + h0 + tx] * g_v[b * LL + o0 + i];
    __syncthreads();
    bf16* hb = g_vthi + (size_t)b * DH * LL;
    bf16* lb = g_vtlo + (size_t)b * DH * LL;
    #pragma unroll
    for (int i = ty; i < 32; i += 8) {
        float x = t[tx][i];
        bf16 h = __float2bfloat16(x);
        bf16 l = __float2bfloat16(x - __bfloat162float(h));
        hb[(size_t)(h0 + i) * LL + o0 + tx] = h;
        lb[(size_t)(h0 + i) * LL + o0 + tx] = l;
    }
}

// ================= small SIMT kernels ========================================
__device__ __forceinline__ float block_reduce_sum_256(float val, float* red) {
    int tid = threadIdx.x;
    #pragma unroll
    for (int o = 16; o > 0; o >>= 1) val += __shfl_down_sync(0xffffffffu, val, o);
    if ((tid & 31) == 0) red[tid >> 5] = val;
    __syncthreads();
    if (tid < 8) {
        val = red[tid];
        #pragma unroll
        for (int o = 4; o > 0; o >>= 1) val += __shfl_down_sync(0xffu, val, o);
        if (tid == 0) red[0] = val;
    }
    __syncthreads();
    float r = red[0];
    __syncthreads();
    return r;
}

__global__ __launch_bounds__(256) void row_invnorm_kernel(
    const float* __restrict__ x, float* __restrict__ inv, float eps)
{
    __shared__ float red[8];
    int row = blockIdx.x;
    const float* p = x + (size_t)row * DH;
    float s = 0.f;
    for (int c = threadIdx.x; c < DH; c += 256) { float v = p[c]; s += v * v; }
    float tot = block_reduce_sum_256(s, red);
    if (threadIdx.x == 0) inv[row] = 1.0f / fmaxf(sqrtf(tot), eps);
}

__global__ void set_ones_kernel(float* p, int n) {
    int i = blockIdx.x * blockDim.x + threadIdx.x;
    if (i < n) p[i] = 1.0f;
}

__global__ void rowmv_kernel(const float* __restrict__ Q,
                             const float* __restrict__ v,
                             float* __restrict__ u)
{
    int t = blockIdx.x * 8 + threadIdx.y;
    int b = blockIdx.y;
    const float* row = Q + ((size_t)b * LL + t) * LL;
    const float* vv = v + b * LL;
    float s = 0.f;
    for (int o = threadIdx.x; o < LL; o += 32) s += row[o] * vv[o];
    #pragma unroll
    for (int off = 16; off > 0; off >>= 1) s += __shfl_down_sync(0xffffffffu, s, off);
    if (threadIdx.x == 0) u[b * LL + t] = 1.0f / s;
}

__global__ void colmv_kernel(const float* __restrict__ Q,
                             const float* __restrict__ u,
                             float* __restrict__ v)
{
    __shared__ float red[8][32];
    int o = blockIdx.x * 32 + threadIdx.x;
    int b = blockIdx.y;
    const float* uu = u + b * LL;
    float s = 0.f;
    for (int t = threadIdx.y; t < LL; t += 8)
        s += Q[((size_t)b * LL + t) * LL + o] * uu[t];
    red[threadIdx.y][threadIdx.x] = s;
    __syncthreads();
    if (threadIdx.y == 0) {
        float tot = 0.f;
        #pragma unroll
        for (int j = 0; j < 8; j++) tot += red[j][threadIdx.x];
        v[b * LL + o] = 1.0f / tot;
    }
}

__global__ void rowscale_kernel(const float* __restrict__ Q,
                                const float* __restrict__ v,
                                const float* __restrict__ u,
                                float* __restrict__ rs)
{
    int t = blockIdx.x * 8 + threadIdx.y;
    int b = blockIdx.y;
    const float* row = Q + ((size_t)b * LL + t) * LL;
    const float* vv = v + b * LL;
    float s = 0.f;
    for (int o = threadIdx.x; o < LL; o += 32) {
        float q = row[o] * vv[o];
        s += q * q;
    }
    #pragma unroll
    for (int off = 16; off > 0; off >>= 1) s += __shfl_down_sync(0xffffffffu, s, off);
    if (threadIdx.x == 0) {
        float ut = u[b * LL + t];
        rs[b * LL + t] = ut / fmaxf(ut * sqrtf(s), 1e-12f);
    }
}

__global__ __launch_bounds__(256) void ln_kernel(
    const float* __restrict__ x, const float* __restrict__ g,
    const float* __restrict__ beta, float* __restrict__ y)
{
    __shared__ float buf[DH];
    __shared__ float red[8];
    int row = blockIdx.x;
    const float* p = x + (size_t)row * DH;
    float s = 0.f;
    for (int c = threadIdx.x; c < DH; c += 256) { float v = p[c]; buf[c] = v; s += v; }
    float mean = block_reduce_sum_256(s, red) * (1.0f / DH);
    float s2 = 0.f;
    for (int c = threadIdx.x; c < DH; c += 256) { float d = buf[c] - mean; s2 += d * d; }
    float var = block_reduce_sum_256(s2, red) * (1.0f / DH);
    float inv = rsqrtf(var + 1e-5f);
    for (int c = threadIdx.x; c < DH; c += 256)
        y[(size_t)row * DH + c] = (buf[c] - mean) * inv * g[c] + beta[c];
}

// ---------------- launch -----------------------------------------------------
extern "C" void kernel_launch(void* const* d_in, const int* in_sizes, int n_in,
                              void* d_out, int out_size)
{
    const float* origin = (const float*)d_in[0];
    const float* target = (const float*)d_in[1];
    const float* W_ori = (const float*)d_in[2];  const float* b_ori = (const float*)d_in[3];
    const float* W_tar = (const float*)d_in[4];  const float* b_tar = (const float*)d_in[5];
    const float* W_ft  = (const float*)d_in[6];  const float* b_ft  = (const float*)d_in[7];
    const float* W_fo  = (const float*)d_in[8];  const float* b_fo  = (const float*)d_in[9];
    const float* W_fot = (const float*)d_in[10]; const float* b_fot = (const float*)d_in[11];
    const float* ln_g  = (const float*)d_in[12]; const float* ln_b  = (const float*)d_in[13];
    float* out = (float*)d_out;

    bf16 *ohi, *olo, *thi, *tlo, *woris_hi, *woris_lo, *wtars_hi, *wtars_lo;
    bf16 *wftT_hi, *wftT_lo, *wfoT_hi, *wfoT_lo, *wfotT_hi, *wfotT_lo;
    float *tar, *ofc, *obuf, *Q, *itn, *ifn, *u, *v, *rs;
    cudaGetSymbolAddress((void**)&ohi,      g_ohi);
    cudaGetSymbolAddress((void**)&olo,      g_olo);
    cudaGetSymbolAddress((void**)&thi,      g_thi);
    cudaGetSymbolAddress((void**)&tlo,      g_tlo);
    cudaGetSymbolAddress((void**)&woris_hi, g_woris_hi);
    cudaGetSymbolAddress((void**)&woris_lo, g_woris_lo);
    cudaGetSymbolAddress((void**)&wtars_hi, g_wtars_hi);
    cudaGetSymbolAddress((void**)&wtars_lo, g_wtars_lo);
    cudaGetSymbolAddress((void**)&wftT_hi,  g_wftT_hi);
    cudaGetSymbolAddress((void**)&wftT_lo,  g_wftT_lo);
    cudaGetSymbolAddress((void**)&wfoT_hi,  g_wfoT_hi);
    cudaGetSymbolAddress((void**)&wfoT_lo,  g_wfoT_lo);
    cudaGetSymbolAddress((void**)&wfotT_hi, g_wfotT_hi);
    cudaGetSymbolAddress((void**)&wfotT_lo, g_wfotT_lo);
    cudaGetSymbolAddress((void**)&tar,      g_tar);
    cudaGetSymbolAddress((void**)&ofc,      g_ofc);
    cudaGetSymbolAddress((void**)&obuf,     g_obuf);
    cudaGetSymbolAddress((void**)&Q,        g_Q);
    cudaGetSymbolAddress((void**)&itn,      g_itn);
    cudaGetSymbolAddress((void**)&ifn,      g_ifn);
    cudaGetSymbolAddress((void**)&u,        g_u);
    cudaGetSymbolAddress((void**)&v,        g_v);
    cudaGetSymbolAddress((void**)&rs,       g_rs);

    const int NELEM = MTOT * DH;
    const int WELEM = (int)WSZ;

    cudaFuncSetAttribute(wgemm3_kernel,
                         cudaFuncAttributeMaxDynamicSharedMemorySize, TC_SMEM);
    cudaFuncSetAttribute(gemm3_tc_kernel,
                         cudaFuncAttributeMaxDynamicSharedMemorySize, TC_SMEM);
    cudaFuncSetAttribute(qgemm_tc_kernel,
                         cudaFuncAttributeMaxDynamicSharedMemorySize, TC_SMEM);
    cudaFuncSetAttribute(fgemm_tc_kernel,
                         cudaFuncAttributeMaxDynamicSharedMemorySize, TC_SMEM);

    dim3 blk(256);

    // splits of activations + plain weight splits
    split_kernel<<<NELEM / 4 / 256, blk>>>(origin, ohi, olo, NELEM);
    split_kernel<<<NELEM / 4 / 256, blk>>>(target, thi, tlo, NELEM);
    split_kernel<<<WELEM / 4 / 256, blk>>>(W_ori, woris_hi, woris_lo, WELEM);
    split_kernel<<<WELEM / 4 / 256, blk>>>(W_tar, wtars_hi, wtars_lo, WELEM);

    // transposed splits of second-stage weights
    dim3 tsg(32, 32), tsb(32, 8);
    trans_split_kernel<<<tsg, tsb>>>(W_ft,  wftT_hi,  wftT_lo);
    trans_split_kernel<<<tsg, tsb>>>(W_fo,  wfoT_hi,  wfoT_lo);
    trans_split_kernel<<<tsg, tsb>>>(W_fot, wfotT_hi, wfotT_lo);

    // composite biases
    bias_comb_kernel<<<dim3(DH / 256, 3), blk>>>(
        b_tar, b_ori, W_ft, W_fo, W_fot, b_ft, b_fo, b_fot);

    // composite weights: WcT[z] via tensor cores (grid 8x8x3 = 192 CTAs)
    wgemm3_kernel<<<dim3(8, 8, 3), blk, TC_SMEM>>>();

    // fused 3 big GEMMs: tar / ofc / otp
    gemm3_tc_kernel<<<dim3(8, 64, 3), blk, TC_SMEM>>>();

    // row inverse norms for cosine similarity
    row_invnorm_kernel<<<MTOT, blk>>>(tar, itn, 1e-8f);
    row_invnorm_kernel<<<MTOT, blk>>>(ofc, ifn, 1e-8f);

    // Q = exp(cos/0.05) on tensor cores, with hi/lo split for the final GEMM
    qgemm_tc_kernel<<<dim3(LL / 128, LL / 128, BB), blk, TC_SMEM>>>();

    // Sinkhorn via scaling vectors: u = 1/(Qv), v = 1/(Q^T u), 5 iterations
    set_ones_kernel<<<(MTOT + 255) / 256, 256>>>(v, MTOT);
    for (int it = 0; it < 5; it++) {
        rowmv_kernel<<<dim3(LL / 8, BB), dim3(32, 8)>>>(Q, v, u);
        colmv_kernel<<<dim3(LL / 32, BB), dim3(32, 8)>>>(Q, u, v);
    }
    rowscale_kernel<<<dim3(LL / 8, BB), dim3(32, 8)>>>(Q, v, u, rs);

    // (v .* otp) transposed + split per batch
    vtrans_split_kernel<<<dim3(DH / 32, LL / 32, BB), tsb>>>();

    // out = rs_t * (Q @ vt^T) + tar on tensor cores
    fgemm_tc_kernel<<<dim3(DH / 128, LL / 128, BB), blk, TC_SMEM>>>();

    // LayerNorm
    ln_kernel<<<MTOT, blk>>>(obuf, ln_g, ln_b, out);
}